// round 6
// baseline (speedup 1.0000x reference)
#include <cuda_runtime.h>

#define TOKENS 100352   // 256 windows * 392 tokens

__device__ float g_qkv[(size_t)TOKENS * 384];   // [token][384]: q*scale | k | v
__device__ float g_att[(size_t)TOKENS * 128];   // attention out, token-major

__device__ __forceinline__ unsigned rna(float f) {
    unsigned u; asm("cvt.rna.tf32.f32 %0, %1;" : "=r"(u) : "f"(f)); return u;
}
__device__ __forceinline__ float u2f(unsigned u) { return __uint_as_float(u); }
__device__ __forceinline__ void mma8(float* d, const unsigned* a, const unsigned* b) {
    asm volatile("mma.sync.aligned.m16n8k8.row.col.f32.tf32.tf32.f32 "
        "{%0,%1,%2,%3}, {%4,%5,%6,%7}, {%8,%9}, {%0,%1,%2,%3};"
        : "+f"(d[0]), "+f"(d[1]), "+f"(d[2]), "+f"(d[3])
        : "r"(a[0]), "r"(a[1]), "r"(a[2]), "r"(a[3]), "r"(b[0]), "r"(b[1]));
}
__device__ __forceinline__ void ldsm4(unsigned* r, unsigned a) {
    asm volatile("ldmatrix.sync.aligned.m8n8.x4.shared.b16 {%0,%1,%2,%3},[%4];"
        : "=r"(r[0]), "=r"(r[1]), "=r"(r[2]), "=r"(r[3]) : "r"(a));
}
__device__ __forceinline__ void ldsm2(unsigned* r, unsigned a) {
    asm volatile("ldmatrix.sync.aligned.m8n8.x2.shared.b16 {%0,%1},[%2];"
        : "=r"(r[0]), "=r"(r[1]) : "r"(a));
}
__device__ __forceinline__ unsigned sptr(const void* p) {
    return (unsigned)__cvta_generic_to_shared(p);
}

// token -> element offset in [B,T,H,W,C] with cyclic shift (+4,+3,+3)
__device__ __forceinline__ int token_img_offset(int m) {
    int win = m / 392;
    int l   = m - win * 392;
    int b   = win >> 7;
    int w2  = win & 127;
    int it  = w2 >> 6, ih = (w2 >> 3) & 7, iw = w2 & 7;
    int lt  = l / 49; int r = l - lt * 49;
    int lh  = r / 7;  int lw = r - lh * 7;
    int t = (it * 8 + lt + 4) & 15;
    int h = ih * 7 + lh + 3; if (h >= 56) h -= 56;
    int w = iw * 7 + lw + 3; if (w >= 56) w -= 56;
    return (((b * 16 + t) * 56 + h) * 56 + w) * 128;
}

// ---------------------------------------------------------------------------
// GEMM core (3xTF32) shared by qkv/proj: 128x128 tile, 512 thr, LDSM operands.
// ---------------------------------------------------------------------------
__device__ __forceinline__ void gemm3_core(
    float* Ah, float* Al, float* Bh, float* Bl,
    int lane, int wm, int wn, float d[2][4][4])
{
    unsigned aoff = sptr(Ah + (wm * 32 + ((lane >> 3) & 1) * 8 + (lane & 7)) * 36
                            + ((lane >> 4) & 1) * 4);
    unsigned boff = sptr(Bh + (wn * 32 + ((lane >> 4) & 1) * 8 + (lane & 7)) * 36
                            + ((lane >> 3) & 1) * 4);
    const unsigned HL = 4608 * 4;        // Ah->Al, Bh->Bl byte offset
    const unsigned R16 = 16 * 36 * 4;    // 16-row byte offset

    #pragma unroll
    for (int ks = 0; ks < 4; ks++) {
        unsigned ka = ks * 32;
        unsigned ah[2][4], al[2][4], bh[2][4], bl[2][4];
        ldsm4(ah[0], aoff + ka);           ldsm4(ah[1], aoff + ka + R16);
        ldsm4(al[0], aoff + ka + HL);      ldsm4(al[1], aoff + ka + HL + R16);
        ldsm4(bh[0], boff + ka);           ldsm4(bh[1], boff + ka + R16);
        ldsm4(bl[0], boff + ka + HL);      ldsm4(bl[1], boff + ka + HL + R16);
        #pragma unroll
        for (int mi = 0; mi < 2; mi++)
            #pragma unroll
            for (int p = 0; p < 2; p++) {
                mma8(d[mi][2 * p],     ah[mi], bh[p]);
                mma8(d[mi][2 * p],     ah[mi], bl[p]);
                mma8(d[mi][2 * p],     al[mi], bh[p]);
                mma8(d[mi][2 * p + 1], ah[mi], bh[p] + 2);
                mma8(d[mi][2 * p + 1], ah[mi], bl[p] + 2);
                mma8(d[mi][2 * p + 1], al[mi], bh[p] + 2);
            }
    }
}

__device__ __forceinline__ void split_store(float v, float* hi, float* lo) {
    float h = u2f(rna(v)); *hi = h; *lo = u2f(rna(v - h));
}

// ---------------------------------------------------------------------------
// Kernel 1: QKV GEMM (3xTF32), fused gather.
// ---------------------------------------------------------------------------
__global__ __launch_bounds__(512, 2) void qkv_kernel(
    const float* __restrict__ x, const float* __restrict__ w,
    const float* __restrict__ bias)
{
    extern __shared__ float sm[];
    float* Ah = sm;                 // [128][36]
    float* Al = Ah + 4608;
    float* Bh = Al + 4608;
    float* Bl = Bh + 4608;
    int* rowsrc = (int*)(Bl + 4608);

    int m0 = blockIdx.x * 128, n0 = blockIdx.y * 128;
    int tid = threadIdx.x;
    if (tid < 128) rowsrc[tid] = token_img_offset(m0 + tid);
    __syncthreads();

    int lane = tid & 31, warp = tid >> 5;
    int wm = warp >> 2, wn = warp & 3;

    float d[2][4][4];
    #pragma unroll
    for (int mi = 0; mi < 2; mi++)
        #pragma unroll
        for (int nj = 0; nj < 4; nj++)
            #pragma unroll
            for (int r = 0; r < 4; r++) d[mi][nj][r] = 0.f;

    for (int kc = 0; kc < 4; kc++) {
        #pragma unroll
        for (int it = 0; it < 2; it++) {
            int idx = tid + it * 512;
            int r = idx >> 3, f4 = idx & 7;
            float4 va = *(const float4*)(x + rowsrc[r] + kc * 32 + f4 * 4);
            split_store(va.x, Ah + r * 36 + f4 * 4 + 0, Al + r * 36 + f4 * 4 + 0);
            split_store(va.y, Ah + r * 36 + f4 * 4 + 1, Al + r * 36 + f4 * 4 + 1);
            split_store(va.z, Ah + r * 36 + f4 * 4 + 2, Al + r * 36 + f4 * 4 + 2);
            split_store(va.w, Ah + r * 36 + f4 * 4 + 3, Al + r * 36 + f4 * 4 + 3);
            float4 vb = *(const float4*)(w + (size_t)(n0 + r) * 128 + kc * 32 + f4 * 4);
            split_store(vb.x, Bh + r * 36 + f4 * 4 + 0, Bl + r * 36 + f4 * 4 + 0);
            split_store(vb.y, Bh + r * 36 + f4 * 4 + 1, Bl + r * 36 + f4 * 4 + 1);
            split_store(vb.z, Bh + r * 36 + f4 * 4 + 2, Bl + r * 36 + f4 * 4 + 2);
            split_store(vb.w, Bh + r * 36 + f4 * 4 + 3, Bl + r * 36 + f4 * 4 + 3);
        }
        __syncthreads();
        gemm3_core(Ah, Al, Bh, Bl, lane, wm, wn, d);
        __syncthreads();
    }

    #pragma unroll
    for (int mi = 0; mi < 2; mi++) {
        int row = m0 + wm * 32 + mi * 16 + (lane >> 2);
        #pragma unroll
        for (int nj = 0; nj < 4; nj++) {
            int col = n0 + wn * 32 + nj * 8 + (lane & 3) * 2;
            float sc = (col < 128) ? 0.17677669529663687f : 1.0f;
            float2 bv = *(const float2*)(bias + col);
            float2 o0, o1;
            o0.x = (d[mi][nj][0] + bv.x) * sc; o0.y = (d[mi][nj][1] + bv.y) * sc;
            o1.x = (d[mi][nj][2] + bv.x) * sc; o1.y = (d[mi][nj][3] + bv.y) * sc;
            *(float2*)(g_qkv + (size_t)row * 384 + col) = o0;
            *(float2*)(g_qkv + (size_t)(row + 8) * 384 + col) = o1;
        }
    }
}

// ---------------------------------------------------------------------------
// Kernel 2: fused attention, LDSM + fused softmax. Block = (win, head), 512 thr.
// Smem: Ks[392][36] | Vt[32][396] | Qs[64][36] | Ss[64][396] | ssum[4][64] | rid
// ---------------------------------------------------------------------------
__global__ __launch_bounds__(512, 1) void attn_kernel(const float* __restrict__ rpb)
{
    extern __shared__ float sm[];
    float* Ks   = sm;                    // 14112
    float* Vt   = Ks + 14112;            // 12672
    float* Qs   = Vt + 12672;            // 2304
    float* Ss   = Qs + 2304;             // 25344
    float* ssum = Ss + 25344;            // 256
    unsigned char* rid = (unsigned char*)(ssum + 256);

    int bx = blockIdx.x;
    int win = bx >> 2, head = bx & 3;
    int tid = threadIdx.x;

    const float* qbase = g_qkv + (size_t)win * (392 * 384) + head * 32;
    const float* kbase = qbase + 128;
    const float* vbase = qbase + 256;

    // region ids for shift mask
    int w2 = win & 127;
    int bt = ((w2 >> 6) == 1), bh = (((w2 >> 3) & 7) == 7), bw = ((w2 & 7) == 7);
    for (int l = tid; l < 392; l += 512) {
        int lt = l / 49; int r = l - lt * 49; int lh = r / 7; int lw = r - lh * 7;
        int rt = bt ? ((lt < 4) ? 1 : 2) : 0;
        int rh = bh ? ((lh < 4) ? 1 : 2) : 0;
        int rw = bw ? ((lw < 4) ? 1 : 2) : 0;
        rid[l] = (unsigned char)(rt * 9 + rh * 3 + rw);
    }
    if (tid < 288) Qs[2016 + tid] = 0.f;   // zero Q pad rows 56..63

    // K rows (tf32), V staged row-major into Ss
    for (int i = tid; i < 392 * 32; i += 512) {
        int j = i >> 5, c = i & 31;
        Ks[j * 36 + c] = u2f(rna(kbase[(size_t)j * 384 + c]));
        Ss[j * 33 + c] = u2f(rna(vbase[(size_t)j * 384 + c]));
    }
    __syncthreads();
    // transpose stage -> Vt[d][j] (conflict-free both sides)
    for (int i = tid; i < 32 * 392; i += 512) {
        int dd = i / 392, j = i - dd * 392;
        Vt[dd * 396 + j] = Ss[j * 33 + dd];
    }

    int lane = tid & 31, warp = tid >> 5;
    int wm = warp >> 2, wn = warp & 3;

    unsigned qs_a = sptr(Qs + (wm * 16 + ((lane >> 3) & 1) * 8 + (lane & 7)) * 36
                            + ((lane >> 4) & 1) * 4);
    unsigned ks_b = sptr(Ks + (lane & 7) * 36 + ((lane >> 3) & 1) * 4);
    unsigned ss_a = sptr(Ss + (wm * 16 + ((lane >> 3) & 1) * 8 + (lane & 7)) * 396
                            + ((lane >> 4) & 1) * 4);
    unsigned vt_b = sptr(Vt + (wn * 8 + (lane & 7)) * 396 + ((lane >> 3) & 1) * 4);

    const float* bhp = rpb + (size_t)head * (392 * 392);

    for (int qt = 0; qt < 7; qt++) {
        int q0 = qt * 56;
        for (int i = tid; i < 56 * 32; i += 512) {
            int q = i >> 5, c = i & 31;
            Qs[q * 36 + c] = u2f(rna(qbase[(size_t)(q0 + q) * 384 + c]));
        }
        __syncthreads();   // Qs ready; prior PV reads of Ss done

        // ---- S = Q K^T ----
        float acc[13][4];
        #pragma unroll
        for (int t = 0; t < 13; t++)
            #pragma unroll
            for (int r = 0; r < 4; r++) acc[t][r] = 0.f;

        #pragma unroll
        for (int ks = 0; ks < 4; ks++) {
            unsigned a[4];
            ldsm4(a, qs_a + ks * 32);
            #pragma unroll
            for (int t = 0; t < 12; t++) {
                unsigned b[2];
                ldsm2(b, ks_b + (unsigned)(wn + 4 * t) * 1152 + ks * 32);
                mma8(acc[t], a, b);
            }
            if (wn == 0) {
                unsigned b[2];
                ldsm2(b, ks_b + 48u * 1152 + ks * 32);
                mma8(acc[12], a, b);
            }
        }

        // ---- epilogue: bias + mask + exp, fused row sums ----
        {
            int qr = wm * 16 + (lane >> 2);
            unsigned char rq0 = rid[q0 + qr];
            unsigned char rq1 = (wm < 3) ? rid[q0 + qr + 8] : (unsigned char)0;
            const float* br0 = bhp + (size_t)(q0 + qr) * 392;
            const float* br1 = br0 + 8 * 392;
            float ps0 = 0.f, ps1 = 0.f;
            #pragma unroll
            for (int t = 0; t < 13; t++) {
                if (t == 12 && wn != 0) break;
                int j = ((t < 12) ? (wn + 4 * t) : 48) * 8 + (lane & 3) * 2;
                unsigned char rj0 = rid[j], rj1 = rid[j + 1];
                float2 b0 = *(const float2*)(br0 + j);
                float e0 = (rq0 == rj0) ? __expf(acc[t][0] + b0.x) : 0.f;
                float e1 = (rq0 == rj1) ? __expf(acc[t][1] + b0.y) : 0.f;
                e0 = u2f(rna(e0)); e1 = u2f(rna(e1));
                float2 w0; w0.x = e0; w0.y = e1;
                *(float2*)(Ss + qr * 396 + j) = w0;
                ps0 += e0 + e1;
                if (wm < 3) {
                    float2 b1 = *(const float2*)(br1 + j);
                    float f0 = (rq1 == rj0) ? __expf(acc[t][2] + b1.x) : 0.f;
                    float f1 = (rq1 == rj1) ? __expf(acc[t][3] + b1.y) : 0.f;
                    f0 = u2f(rna(f0)); f1 = u2f(rna(f1));
                    float2 w1; w1.x = f0; w1.y = f1;
                    *(float2*)(Ss + (qr + 8) * 396 + j) = w1;
                    ps1 += f0 + f1;
                }
            }
            ps0 += __shfl_xor_sync(0xffffffffu, ps0, 1);
            ps0 += __shfl_xor_sync(0xffffffffu, ps0, 2);
            ps1 += __shfl_xor_sync(0xffffffffu, ps1, 1);
            ps1 += __shfl_xor_sync(0xffffffffu, ps1, 2);
            if ((lane & 3) == 0) {
                ssum[wn * 64 + qr] = ps0;
                if (wm < 3) ssum[wn * 64 + qr + 8] = ps1;
            }
        }
        __syncthreads();

        // ---- PV: warp (wm, wn) -> 16x8 tile, K = 392 ----
        {
            float pacc[4] = {0.f, 0.f, 0.f, 0.f};
            #pragma unroll 7
            for (int ks = 0; ks < 49; ks++) {
                unsigned a[4], b[2];
                ldsm4(a, ss_a + ks * 32);
                ldsm2(b, vt_b + ks * 32);
                mma8(pacc, a, b);
            }
            int par = wm * 16 + (lane >> 2);
            int dc = wn * 8 + (lane & 3) * 2;
            float si0 = 1.f / (ssum[par] + ssum[64 + par] + ssum[128 + par] + ssum[192 + par]);
            size_t ob0 = ((size_t)win * 392 + q0 + par) * 128 + head * 32 + dc;
            float2 o0; o0.x = pacc[0] * si0; o0.y = pacc[1] * si0;
            *(float2*)(g_att + ob0) = o0;
            if (wm < 3) {
                int pr1 = par + 8;
                float si1 = 1.f / (ssum[pr1] + ssum[64 + pr1] + ssum[128 + pr1] + ssum[192 + pr1]);
                float2 o1; o1.x = pacc[2] * si1; o1.y = pacc[3] * si1;
                *(float2*)(g_att + ob0 + 8 * 128) = o1;
            }
        }
        __syncthreads();   // Ss/ssum reads done before next qt writes
    }
}

// ---------------------------------------------------------------------------
// Kernel 3: proj GEMM (3xTF32), fused scatter.
// ---------------------------------------------------------------------------
__global__ __launch_bounds__(512, 2) void proj_kernel(
    const float* __restrict__ w, const float* __restrict__ bias,
    float* __restrict__ out)
{
    extern __shared__ float sm[];
    float* Ah = sm;
    float* Al = Ah + 4608;
    float* Bh = Al + 4608;
    float* Bl = Bh + 4608;
    int* rowdst = (int*)(Bl + 4608);

    int m0 = blockIdx.x * 128;
    int tid = threadIdx.x;
    if (tid < 128) rowdst[tid] = token_img_offset(m0 + tid);
    __syncthreads();

    int lane = tid & 31, warp = tid >> 5;
    int wm = warp >> 2, wn = warp & 3;

    float d[2][4][4];
    #pragma unroll
    for (int mi = 0; mi < 2; mi++)
        #pragma unroll
        for (int nj = 0; nj < 4; nj++)
            #pragma unroll
            for (int r = 0; r < 4; r++) d[mi][nj][r] = 0.f;

    for (int kc = 0; kc < 4; kc++) {
        #pragma unroll
        for (int it = 0; it < 2; it++) {
            int idx = tid + it * 512;
            int r = idx >> 3, f4 = idx & 7;
            float4 va = *(const float4*)(g_att + (size_t)(m0 + r) * 128 + kc * 32 + f4 * 4);
            split_store(va.x, Ah + r * 36 + f4 * 4 + 0, Al + r * 36 + f4 * 4 + 0);
            split_store(va.y, Ah + r * 36 + f4 * 4 + 1, Al + r * 36 + f4 * 4 + 1);
            split_store(va.z, Ah + r * 36 + f4 * 4 + 2, Al + r * 36 + f4 * 4 + 2);
            split_store(va.w, Ah + r * 36 + f4 * 4 + 3, Al + r * 36 + f4 * 4 + 3);
            float4 vb = *(const float4*)(w + (size_t)r * 128 + kc * 32 + f4 * 4);
            split_store(vb.x, Bh + r * 36 + f4 * 4 + 0, Bl + r * 36 + f4 * 4 + 0);
            split_store(vb.y, Bh + r * 36 + f4 * 4 + 1, Bl + r * 36 + f4 * 4 + 1);
            split_store(vb.z, Bh + r * 36 + f4 * 4 + 2, Bl + r * 36 + f4 * 4 + 2);
            split_store(vb.w, Bh + r * 36 + f4 * 4 + 3, Bl + r * 36 + f4 * 4 + 3);
        }
        __syncthreads();
        gemm3_core(Ah, Al, Bh, Bl, lane, wm, wn, d);
        __syncthreads();
    }

    #pragma unroll
    for (int mi = 0; mi < 2; mi++) {
        int ml = wm * 32 + mi * 16 + (lane >> 2);
        #pragma unroll
        for (int nj = 0; nj < 4; nj++) {
            int col = wn * 32 + nj * 8 + (lane & 3) * 2;
            float2 bv = *(const float2*)(bias + col);
            float2 o0, o1;
            o0.x = d[mi][nj][0] + bv.x; o0.y = d[mi][nj][1] + bv.y;
            o1.x = d[mi][nj][2] + bv.x; o1.y = d[mi][nj][3] + bv.y;
            *(float2*)(out + rowdst[ml] + col) = o0;
            *(float2*)(out + rowdst[ml + 8] + col) = o1;
        }
    }
}

// ---------------------------------------------------------------------------
extern "C" void kernel_launch(void* const* d_in, const int* in_sizes, int n_in,
                              void* d_out, int out_size)
{
    const float* x   = (const float*)d_in[0];
    const float* qw  = (const float*)d_in[1];
    const float* qb  = (const float*)d_in[2];
    const float* pw  = (const float*)d_in[3];
    const float* pb  = (const float*)d_in[4];
    const float* rpb = (const float*)d_in[5];
    float* out = (float*)d_out;

    const int smemG = 4 * 4608 * 4 + 128 * 4;        // 74,240 B
    const int smemA = 54688 * 4 + 392 + 8;           // 219,152 B

    cudaFuncSetAttribute(qkv_kernel,  cudaFuncAttributeMaxDynamicSharedMemorySize, smemG);
    cudaFuncSetAttribute(attn_kernel, cudaFuncAttributeMaxDynamicSharedMemorySize, smemA);
    cudaFuncSetAttribute(proj_kernel, cudaFuncAttributeMaxDynamicSharedMemorySize, smemG);

    qkv_kernel<<<dim3(784, 3), 512, smemG>>>(x, qw, qb);
    attn_kernel<<<1024, 512, smemA>>>(rpb);
    proj_kernel<<<784, 512, smemG>>>(pw, pb, out);
}

// round 7
// speedup vs baseline: 1.3716x; 1.3716x over previous
#include <cuda_runtime.h>

#define TOKENS 100352   // 256 windows * 392 tokens

__device__ float g_qkv[(size_t)TOKENS * 384];   // [token][384]: q*scale | k | v
__device__ float g_att[(size_t)TOKENS * 128];   // attention out, token-major

__device__ __forceinline__ unsigned rna(float f) {
    unsigned u; asm("cvt.rna.tf32.f32 %0, %1;" : "=r"(u) : "f"(f)); return u;
}
__device__ __forceinline__ float u2f(unsigned u) { return __uint_as_float(u); }
__device__ __forceinline__ unsigned f2u(float f) { return __float_as_uint(f); }
__device__ __forceinline__ void mma8(float* d, const unsigned* a, const unsigned* b) {
    asm volatile("mma.sync.aligned.m16n8k8.row.col.f32.tf32.tf32.f32 "
        "{%0,%1,%2,%3}, {%4,%5,%6,%7}, {%8,%9}, {%0,%1,%2,%3};"
        : "+f"(d[0]), "+f"(d[1]), "+f"(d[2]), "+f"(d[3])
        : "r"(a[0]), "r"(a[1]), "r"(a[2]), "r"(a[3]), "r"(b[0]), "r"(b[1]));
}
__device__ __forceinline__ void ldsm4(unsigned* r, unsigned a) {
    asm volatile("ldmatrix.sync.aligned.m8n8.x4.shared.b16 {%0,%1,%2,%3},[%4];"
        : "=r"(r[0]), "=r"(r[1]), "=r"(r[2]), "=r"(r[3]) : "r"(a));
}
__device__ __forceinline__ void ldsm2(unsigned* r, unsigned a) {
    asm volatile("ldmatrix.sync.aligned.m8n8.x2.shared.b16 {%0,%1},[%2];"
        : "=r"(r[0]), "=r"(r[1]) : "r"(a));
}
__device__ __forceinline__ unsigned sptr(const void* p) {
    return (unsigned)__cvta_generic_to_shared(p);
}

// token -> element offset in [B,T,H,W,C] with cyclic shift (+4,+3,+3)
__device__ __forceinline__ int token_img_offset(int m) {
    int win = m / 392;
    int l   = m - win * 392;
    int b   = win >> 7;
    int w2  = win & 127;
    int it  = w2 >> 6, ih = (w2 >> 3) & 7, iw = w2 & 7;
    int lt  = l / 49; int r = l - lt * 49;
    int lh  = r / 7;  int lw = r - lh * 7;
    int t = (it * 8 + lt + 4) & 15;
    int h = ih * 7 + lh + 3; if (h >= 56) h -= 56;
    int w = iw * 7 + lw + 3; if (w >= 56) w -= 56;
    return (((b * 16 + t) * 56 + h) * 56 + w) * 128;
}

// ---------------------------------------------------------------------------
// GEMM core (3xTF32) shared by qkv/proj: 128x128 tile, 512 thr, LDSM operands.
// ---------------------------------------------------------------------------
__device__ __forceinline__ void gemm3_core(
    float* Ah, float* Al, float* Bh, float* Bl,
    int lane, int wm, int wn, float d[2][4][4])
{
    unsigned aoff = sptr(Ah + (wm * 32 + ((lane >> 3) & 1) * 8 + (lane & 7)) * 36
                            + ((lane >> 4) & 1) * 4);
    unsigned boff = sptr(Bh + (wn * 32 + ((lane >> 4) & 1) * 8 + (lane & 7)) * 36
                            + ((lane >> 3) & 1) * 4);
    const unsigned HL = 4608 * 4;
    const unsigned R16 = 16 * 36 * 4;

    #pragma unroll
    for (int ks = 0; ks < 4; ks++) {
        unsigned ka = ks * 32;
        unsigned ah[2][4], al[2][4], bh[2][4], bl[2][4];
        ldsm4(ah[0], aoff + ka);           ldsm4(ah[1], aoff + ka + R16);
        ldsm4(al[0], aoff + ka + HL);      ldsm4(al[1], aoff + ka + HL + R16);
        ldsm4(bh[0], boff + ka);           ldsm4(bh[1], boff + ka + R16);
        ldsm4(bl[0], boff + ka + HL);      ldsm4(bl[1], boff + ka + HL + R16);
        #pragma unroll
        for (int mi = 0; mi < 2; mi++)
            #pragma unroll
            for (int p = 0; p < 2; p++) {
                mma8(d[mi][2 * p],     ah[mi], bh[p]);
                mma8(d[mi][2 * p],     ah[mi], bl[p]);
                mma8(d[mi][2 * p],     al[mi], bh[p]);
                mma8(d[mi][2 * p + 1], ah[mi], bh[p] + 2);
                mma8(d[mi][2 * p + 1], ah[mi], bl[p] + 2);
                mma8(d[mi][2 * p + 1], al[mi], bh[p] + 2);
            }
    }
}

__device__ __forceinline__ void split_store(float v, float* hi, float* lo) {
    float h = u2f(rna(v)); *hi = h; *lo = u2f(rna(v - h));
}

// ---------------------------------------------------------------------------
// Kernel 1: QKV GEMM (3xTF32), fused gather. grid (3, 784): n fastest -> x L2 reuse.
// ---------------------------------------------------------------------------
__global__ __launch_bounds__(512, 2) void qkv_kernel(
    const float* __restrict__ x, const float* __restrict__ w,
    const float* __restrict__ bias)
{
    extern __shared__ float sm[];
    float* Ah = sm;                 // [128][36]
    float* Al = Ah + 4608;
    float* Bh = Al + 4608;
    float* Bl = Bh + 4608;
    int* rowsrc = (int*)(Bl + 4608);

    int m0 = blockIdx.y * 128, n0 = blockIdx.x * 128;
    int tid = threadIdx.x;
    if (tid < 128) rowsrc[tid] = token_img_offset(m0 + tid);
    __syncthreads();

    int lane = tid & 31, warp = tid >> 5;
    int wm = warp >> 2, wn = warp & 3;

    float d[2][4][4];
    #pragma unroll
    for (int mi = 0; mi < 2; mi++)
        #pragma unroll
        for (int nj = 0; nj < 4; nj++)
            #pragma unroll
            for (int r = 0; r < 4; r++) d[mi][nj][r] = 0.f;

    for (int kc = 0; kc < 4; kc++) {
        #pragma unroll
        for (int it = 0; it < 2; it++) {
            int idx = tid + it * 512;
            int r = idx >> 3, f4 = idx & 7;
            float4 va = *(const float4*)(x + rowsrc[r] + kc * 32 + f4 * 4);
            split_store(va.x, Ah + r * 36 + f4 * 4 + 0, Al + r * 36 + f4 * 4 + 0);
            split_store(va.y, Ah + r * 36 + f4 * 4 + 1, Al + r * 36 + f4 * 4 + 1);
            split_store(va.z, Ah + r * 36 + f4 * 4 + 2, Al + r * 36 + f4 * 4 + 2);
            split_store(va.w, Ah + r * 36 + f4 * 4 + 3, Al + r * 36 + f4 * 4 + 3);
            float4 vb = *(const float4*)(w + (size_t)(n0 + r) * 128 + kc * 32 + f4 * 4);
            split_store(vb.x, Bh + r * 36 + f4 * 4 + 0, Bl + r * 36 + f4 * 4 + 0);
            split_store(vb.y, Bh + r * 36 + f4 * 4 + 1, Bl + r * 36 + f4 * 4 + 1);
            split_store(vb.z, Bh + r * 36 + f4 * 4 + 2, Bl + r * 36 + f4 * 4 + 2);
            split_store(vb.w, Bh + r * 36 + f4 * 4 + 3, Bl + r * 36 + f4 * 4 + 3);
        }
        __syncthreads();
        gemm3_core(Ah, Al, Bh, Bl, lane, wm, wn, d);
        __syncthreads();
    }

    #pragma unroll
    for (int mi = 0; mi < 2; mi++) {
        int row = m0 + wm * 32 + mi * 16 + (lane >> 2);
        #pragma unroll
        for (int nj = 0; nj < 4; nj++) {
            int col = n0 + wn * 32 + nj * 8 + (lane & 3) * 2;
            float sc = (col < 128) ? 0.17677669529663687f : 1.0f;
            float2 bv = *(const float2*)(bias + col);
            float2 o0, o1;
            o0.x = (d[mi][nj][0] + bv.x) * sc; o0.y = (d[mi][nj][1] + bv.y) * sc;
            o1.x = (d[mi][nj][2] + bv.x) * sc; o1.y = (d[mi][nj][3] + bv.y) * sc;
            *(float2*)(g_qkv + (size_t)row * 384 + col) = o0;
            *(float2*)(g_qkv + (size_t)(row + 8) * 384 + col) = o1;
        }
    }
}

// ---------------------------------------------------------------------------
// Kernel 2: single-pass flash attention. Block = (win, head), 512 thr, 1 sync.
// Smem: Ks[392][36] | Vt[32][396] | Qs[400][36] | rid[392]
// Per warp: 16-row q-tile, stream 49 j-tiles: S mma -> exp -> shfl relayout -> PV mma.
// ---------------------------------------------------------------------------
__global__ __launch_bounds__(512, 1) void attn_kernel(const float* __restrict__ rpb)
{
    extern __shared__ float sm[];
    float* Ks = sm;                      // 392*36 = 14112
    float* Vt = Ks + 14112;              // 32*396 = 12672
    float* Qs = Vt + 12672;              // 400*36 = 14400
    unsigned char* rid = (unsigned char*)(Qs + 14400);

    int bx = blockIdx.x;
    int win = bx >> 2, head = bx & 3;
    int tid = threadIdx.x;

    const float* qbase = g_qkv + (size_t)win * (392 * 384) + head * 32;
    const float* kbase = qbase + 128;
    const float* vbase = qbase + 256;

    // region ids for shift mask
    int w2 = win & 127;
    int bt = ((w2 >> 6) == 1), bh = (((w2 >> 3) & 7) == 7), bw = ((w2 & 7) == 7);
    for (int l = tid; l < 392; l += 512) {
        int lt = l / 49; int r = l - lt * 49; int lh = r / 7; int lw = r - lh * 7;
        int rt = bt ? ((lt < 4) ? 1 : 2) : 0;
        int rh = bh ? ((lh < 4) ? 1 : 2) : 0;
        int rw = bw ? ((lw < 4) ? 1 : 2) : 0;
        rid[l] = (unsigned char)(rt * 9 + rh * 3 + rw);
    }
    // K rows (float4, tf32)
    for (int i = tid; i < 392 * 8; i += 512) {
        int j = i >> 3, c4 = i & 7;
        float4 v = *(const float4*)(kbase + (size_t)j * 384 + c4 * 4);
        float* d = Ks + j * 36 + c4 * 4;
        d[0] = u2f(rna(v.x)); d[1] = u2f(rna(v.y));
        d[2] = u2f(rna(v.z)); d[3] = u2f(rna(v.w));
    }
    // V transposed (scalar; 4-way STS conflict, one-time)
    for (int i = tid; i < 392 * 32; i += 512) {
        int j = i >> 5, c = i & 31;
        Vt[c * 396 + j] = u2f(rna(vbase[(size_t)j * 384 + c]));
    }
    // Q rows + zero pad rows 392..399
    for (int i = tid; i < 400 * 8; i += 512) {
        int q = i >> 3, c4 = i & 7;
        float4 v = (q < 392) ? *(const float4*)(qbase + (size_t)q * 384 + c4 * 4)
                             : make_float4(0.f, 0.f, 0.f, 0.f);
        float* d = Qs + q * 36 + c4 * 4;
        d[0] = u2f(rna(v.x)); d[1] = u2f(rna(v.y));
        d[2] = u2f(rna(v.z)); d[3] = u2f(rna(v.w));
    }
    __syncthreads();   // the only block-wide sync

    int lane = tid & 31, warp = tid >> 5;
    const float* bhp = rpb + (size_t)head * (392 * 392);

    unsigned ksb = sptr(Ks + (lane & 7) * 36 + ((lane >> 3) & 1) * 4);
    unsigned vtb = sptr(Vt + (lane & 7) * 396 + ((lane >> 3) & 1) * 4);
    int qsrc1 = (lane & ~3) | ((lane & 3) >> 1);
    int qsrc2 = qsrc1 + 2;
    bool odd = (lane & 1);

    for (int mt = warp; mt < 25; mt += 16) {
        int q0m = mt * 16;
        // A fragments for this q-tile (k = 0..31)
        unsigned aoff = sptr(Qs + (q0m + ((lane >> 3) & 1) * 8 + (lane & 7)) * 36
                                + ((lane >> 4) & 1) * 4);
        unsigned a[4][4];
        #pragma unroll
        for (int ks = 0; ks < 4; ks++) ldsm4(a[ks], aoff + ks * 32);

        int qr = q0m + (lane >> 2);
        int qc0 = (qr < 392) ? qr : 391;
        int qc1 = (qr + 8 < 392) ? (qr + 8) : 391;
        unsigned char rq0 = rid[qc0], rq1 = rid[qc1];
        const float* br0 = bhp + (size_t)qc0 * 392;
        const float* br1 = bhp + (size_t)qc1 * 392;

        float oacc[4][4];
        #pragma unroll
        for (int dt = 0; dt < 4; dt++)
            #pragma unroll
            for (int r = 0; r < 4; r++) oacc[dt][r] = 0.f;
        float rs0 = 0.f, rs1 = 0.f;

        #pragma unroll 2
        for (int jt = 0; jt < 49; jt++) {
            // S = Q K^T (16x8)
            float s[4] = {0.f, 0.f, 0.f, 0.f};
            unsigned kb = ksb + (unsigned)jt * 1152;   // 8 rows * 36 * 4B
            #pragma unroll
            for (int ks = 0; ks < 4; ks++) {
                unsigned b[2];
                ldsm2(b, kb + ks * 32);
                mma8(s, a[ks], b);
            }
            // bias + mask + exp
            int jc = jt * 8 + 2 * (lane & 3);
            unsigned char rj0 = rid[jc], rj1 = rid[jc + 1];
            float2 b0 = *(const float2*)(br0 + jc);
            float2 b1 = *(const float2*)(br1 + jc);
            float e0 = (rq0 == rj0) ? u2f(rna(__expf(s[0] + b0.x))) : 0.f;
            float e1 = (rq0 == rj1) ? u2f(rna(__expf(s[1] + b0.y))) : 0.f;
            float e2 = (rq1 == rj0) ? u2f(rna(__expf(s[2] + b1.x))) : 0.f;
            float e3 = (rq1 == rj1) ? u2f(rna(__expf(s[3] + b1.y))) : 0.f;
            rs0 += e0 + e1;
            rs1 += e2 + e3;
            // relayout C-frag -> A-frag (cols 2i,2i+1 -> i, i+4)
            float t00 = __shfl_sync(0xffffffffu, e0, qsrc1);
            float t01 = __shfl_sync(0xffffffffu, e1, qsrc1);
            float t10 = __shfl_sync(0xffffffffu, e2, qsrc1);
            float t11 = __shfl_sync(0xffffffffu, e3, qsrc1);
            float u00 = __shfl_sync(0xffffffffu, e0, qsrc2);
            float u01 = __shfl_sync(0xffffffffu, e1, qsrc2);
            float u10 = __shfl_sync(0xffffffffu, e2, qsrc2);
            float u11 = __shfl_sync(0xffffffffu, e3, qsrc2);
            unsigned pa[4];
            pa[0] = f2u(odd ? t01 : t00);
            pa[1] = f2u(odd ? t11 : t10);
            pa[2] = f2u(odd ? u01 : u00);
            pa[3] = f2u(odd ? u11 : u10);
            // PV: P(16x8) x V(8x32)
            unsigned vb0 = vtb + (unsigned)jt * 32;
            #pragma unroll
            for (int dt = 0; dt < 4; dt++) {
                unsigned b[2];
                ldsm2(b, vb0 + (unsigned)dt * 12672);   // 8 rows * 396 * 4B
                mma8(oacc[dt], pa, b);
            }
        }

        // quad-reduce row sums (all lanes get result)
        rs0 += __shfl_xor_sync(0xffffffffu, rs0, 1);
        rs0 += __shfl_xor_sync(0xffffffffu, rs0, 2);
        rs1 += __shfl_xor_sync(0xffffffffu, rs1, 1);
        rs1 += __shfl_xor_sync(0xffffffffu, rs1, 2);
        float si0 = 1.f / rs0, si1 = 1.f / rs1;

        size_t ob = ((size_t)win * 392 + qr) * 128 + head * 32;
        #pragma unroll
        for (int dt = 0; dt < 4; dt++) {
            int dc = dt * 8 + 2 * (lane & 3);
            float2 o0; o0.x = oacc[dt][0] * si0; o0.y = oacc[dt][1] * si0;
            *(float2*)(g_att + ob + dc) = o0;
            if (qr + 8 < 392) {
                float2 o1; o1.x = oacc[dt][2] * si1; o1.y = oacc[dt][3] * si1;
                *(float2*)(g_att + ob + 8 * 128 + dc) = o1;
            }
        }
    }
}

// ---------------------------------------------------------------------------
// Kernel 3: proj GEMM (3xTF32), fused scatter.
// ---------------------------------------------------------------------------
__global__ __launch_bounds__(512, 2) void proj_kernel(
    const float* __restrict__ w, const float* __restrict__ bias,
    float* __restrict__ out)
{
    extern __shared__ float sm[];
    float* Ah = sm;
    float* Al = Ah + 4608;
    float* Bh = Al + 4608;
    float* Bl = Bh + 4608;
    int* rowdst = (int*)(Bl + 4608);

    int m0 = blockIdx.x * 128;
    int tid = threadIdx.x;
    if (tid < 128) rowdst[tid] = token_img_offset(m0 + tid);
    __syncthreads();

    int lane = tid & 31, warp = tid >> 5;
    int wm = warp >> 2, wn = warp & 3;

    float d[2][4][4];
    #pragma unroll
    for (int mi = 0; mi < 2; mi++)
        #pragma unroll
        for (int nj = 0; nj < 4; nj++)
            #pragma unroll
            for (int r = 0; r < 4; r++) d[mi][nj][r] = 0.f;

    for (int kc = 0; kc < 4; kc++) {
        #pragma unroll
        for (int it = 0; it < 2; it++) {
            int idx = tid + it * 512;
            int r = idx >> 3, f4 = idx & 7;
            float4 va = *(const float4*)(g_att + (size_t)(m0 + r) * 128 + kc * 32 + f4 * 4);
            split_store(va.x, Ah + r * 36 + f4 * 4 + 0, Al + r * 36 + f4 * 4 + 0);
            split_store(va.y, Ah + r * 36 + f4 * 4 + 1, Al + r * 36 + f4 * 4 + 1);
            split_store(va.z, Ah + r * 36 + f4 * 4 + 2, Al + r * 36 + f4 * 4 + 2);
            split_store(va.w, Ah + r * 36 + f4 * 4 + 3, Al + r * 36 + f4 * 4 + 3);
            float4 vb = *(const float4*)(w + (size_t)r * 128 + kc * 32 + f4 * 4);
            split_store(vb.x, Bh + r * 36 + f4 * 4 + 0, Bl + r * 36 + f4 * 4 + 0);
            split_store(vb.y, Bh + r * 36 + f4 * 4 + 1, Bl + r * 36 + f4 * 4 + 1);
            split_store(vb.z, Bh + r * 36 + f4 * 4 + 2, Bl + r * 36 + f4 * 4 + 2);
            split_store(vb.w, Bh + r * 36 + f4 * 4 + 3, Bl + r * 36 + f4 * 4 + 3);
        }
        __syncthreads();
        gemm3_core(Ah, Al, Bh, Bl, lane, wm, wn, d);
        __syncthreads();
    }

    #pragma unroll
    for (int mi = 0; mi < 2; mi++) {
        int ml = wm * 32 + mi * 16 + (lane >> 2);
        #pragma unroll
        for (int nj = 0; nj < 4; nj++) {
            int col = wn * 32 + nj * 8 + (lane & 3) * 2;
            float2 bv = *(const float2*)(bias + col);
            float2 o0, o1;
            o0.x = d[mi][nj][0] + bv.x; o0.y = d[mi][nj][1] + bv.y;
            o1.x = d[mi][nj][2] + bv.x; o1.y = d[mi][nj][3] + bv.y;
            *(float2*)(out + rowdst[ml] + col) = o0;
            *(float2*)(out + rowdst[ml + 8] + col) = o1;
        }
    }
}

// ---------------------------------------------------------------------------
extern "C" void kernel_launch(void* const* d_in, const int* in_sizes, int n_in,
                              void* d_out, int out_size)
{
    const float* x   = (const float*)d_in[0];
    const float* qw  = (const float*)d_in[1];
    const float* qb  = (const float*)d_in[2];
    const float* pw  = (const float*)d_in[3];
    const float* pb  = (const float*)d_in[4];
    const float* rpb = (const float*)d_in[5];
    float* out = (float*)d_out;

    const int smemG = 4 * 4608 * 4 + 128 * 4;               // 74,240 B
    const int smemA = (14112 + 12672 + 14400) * 4 + 392 + 8; // 165,136 B

    cudaFuncSetAttribute(qkv_kernel,  cudaFuncAttributeMaxDynamicSharedMemorySize, smemG);
    cudaFuncSetAttribute(attn_kernel, cudaFuncAttributeMaxDynamicSharedMemorySize, smemA);
    cudaFuncSetAttribute(proj_kernel, cudaFuncAttributeMaxDynamicSharedMemorySize, smemG);

    qkv_kernel<<<dim3(3, 784), 512, smemG>>>(x, qw, qb);
    attn_kernel<<<1024, 512, smemA>>>(rpb);
    proj_kernel<<<784, 512, smemG>>>(pw, pb, out);
}

// round 8
// speedup vs baseline: 1.8680x; 1.3620x over previous
#include <cuda_runtime.h>

#define TOKENS 100352   // 256 windows * 392 tokens

__device__ float g_qkv[(size_t)TOKENS * 384];   // [token][384]: q*scale | k | v
__device__ float g_att[(size_t)TOKENS * 128];   // attention out, token-major

__device__ __forceinline__ unsigned rna(float f) {
    unsigned u; asm("cvt.rna.tf32.f32 %0, %1;" : "=r"(u) : "f"(f)); return u;
}
__device__ __forceinline__ float u2f(unsigned u) { return __uint_as_float(u); }
__device__ __forceinline__ unsigned f2u(float f) { return __float_as_uint(f); }
__device__ __forceinline__ void mma8(float* d, const unsigned* a, const unsigned* b) {
    asm volatile("mma.sync.aligned.m16n8k8.row.col.f32.tf32.tf32.f32 "
        "{%0,%1,%2,%3}, {%4,%5,%6,%7}, {%8,%9}, {%0,%1,%2,%3};"
        : "+f"(d[0]), "+f"(d[1]), "+f"(d[2]), "+f"(d[3])
        : "r"(a[0]), "r"(a[1]), "r"(a[2]), "r"(a[3]), "r"(b[0]), "r"(b[1]));
}
__device__ __forceinline__ void ldsm4(unsigned* r, unsigned a) {
    asm volatile("ldmatrix.sync.aligned.m8n8.x4.shared.b16 {%0,%1,%2,%3},[%4];"
        : "=r"(r[0]), "=r"(r[1]), "=r"(r[2]), "=r"(r[3]) : "r"(a));
}
__device__ __forceinline__ void ldsm2(unsigned* r, unsigned a) {
    asm volatile("ldmatrix.sync.aligned.m8n8.x2.shared.b16 {%0,%1},[%2];"
        : "=r"(r[0]), "=r"(r[1]) : "r"(a));
}
__device__ __forceinline__ unsigned sptr(const void* p) {
    return (unsigned)__cvta_generic_to_shared(p);
}

// token -> element offset in [B,T,H,W,C] with cyclic shift (+4,+3,+3)
__device__ __forceinline__ int token_img_offset(int m) {
    int win = m / 392;
    int l   = m - win * 392;
    int b   = win >> 7;
    int w2  = win & 127;
    int it  = w2 >> 6, ih = (w2 >> 3) & 7, iw = w2 & 7;
    int lt  = l / 49; int r = l - lt * 49;
    int lh  = r / 7;  int lw = r - lh * 7;
    int t = (it * 8 + lt + 4) & 15;
    int h = ih * 7 + lh + 3; if (h >= 56) h -= 56;
    int w = iw * 7 + lw + 3; if (w >= 56) w -= 56;
    return (((b * 16 + t) * 56 + h) * 56 + w) * 128;
}

// ---------------------------------------------------------------------------
// 1xTF32 GEMM core: 128x128 tile, 512 thr, LDSM operands.
// ---------------------------------------------------------------------------
__device__ __forceinline__ void gemm1_core(
    float* As, float* Bs, int lane, int wm, int wn, float d[2][4][4])
{
    unsigned aoff = sptr(As + (wm * 32 + ((lane >> 3) & 1) * 8 + (lane & 7)) * 36
                            + ((lane >> 4) & 1) * 4);
    unsigned boff = sptr(Bs + (wn * 32 + ((lane >> 4) & 1) * 8 + (lane & 7)) * 36
                            + ((lane >> 3) & 1) * 4);
    const unsigned R16 = 16 * 36 * 4;

    #pragma unroll
    for (int ks = 0; ks < 4; ks++) {
        unsigned ka = ks * 32;
        unsigned a[2][4], b[2][4];
        ldsm4(a[0], aoff + ka);  ldsm4(a[1], aoff + ka + R16);
        ldsm4(b[0], boff + ka);  ldsm4(b[1], boff + ka + R16);
        #pragma unroll
        for (int mi = 0; mi < 2; mi++)
            #pragma unroll
            for (int p = 0; p < 2; p++) {
                mma8(d[mi][2 * p],     a[mi], b[p]);
                mma8(d[mi][2 * p + 1], a[mi], b[p] + 2);
            }
    }
}

// ---------------------------------------------------------------------------
// Kernel 1: QKV GEMM (1xTF32), fused gather. grid (3, 784).
// ---------------------------------------------------------------------------
__global__ __launch_bounds__(512, 2) void qkv_kernel(
    const float* __restrict__ x, const float* __restrict__ w,
    const float* __restrict__ bias)
{
    extern __shared__ float sm[];
    float* As = sm;                 // [128][36]
    float* Bs = As + 4608;
    int* rowsrc = (int*)(Bs + 4608);

    int m0 = blockIdx.y * 128, n0 = blockIdx.x * 128;
    int tid = threadIdx.x;
    if (tid < 128) rowsrc[tid] = token_img_offset(m0 + tid);
    __syncthreads();

    int lane = tid & 31, warp = tid >> 5;
    int wm = warp >> 2, wn = warp & 3;

    float d[2][4][4];
    #pragma unroll
    for (int mi = 0; mi < 2; mi++)
        #pragma unroll
        for (int nj = 0; nj < 4; nj++)
            #pragma unroll
            for (int r = 0; r < 4; r++) d[mi][nj][r] = 0.f;

    for (int kc = 0; kc < 4; kc++) {
        #pragma unroll
        for (int it = 0; it < 2; it++) {
            int idx = tid + it * 512;
            int r = idx >> 3, f4 = idx & 7;
            float4 va = *(const float4*)(x + rowsrc[r] + kc * 32 + f4 * 4);
            float* ad = As + r * 36 + f4 * 4;
            ad[0] = u2f(rna(va.x)); ad[1] = u2f(rna(va.y));
            ad[2] = u2f(rna(va.z)); ad[3] = u2f(rna(va.w));
            float4 vb = *(const float4*)(w + (size_t)(n0 + r) * 128 + kc * 32 + f4 * 4);
            float* bd = Bs + r * 36 + f4 * 4;
            bd[0] = u2f(rna(vb.x)); bd[1] = u2f(rna(vb.y));
            bd[2] = u2f(rna(vb.z)); bd[3] = u2f(rna(vb.w));
        }
        __syncthreads();
        gemm1_core(As, Bs, lane, wm, wn, d);
        __syncthreads();
    }

    #pragma unroll
    for (int mi = 0; mi < 2; mi++) {
        int row = m0 + wm * 32 + mi * 16 + (lane >> 2);
        #pragma unroll
        for (int nj = 0; nj < 4; nj++) {
            int col = n0 + wn * 32 + nj * 8 + (lane & 3) * 2;
            float sc = (col < 128) ? 0.17677669529663687f : 1.0f;
            float2 bv = *(const float2*)(bias + col);
            float2 o0, o1;
            o0.x = (d[mi][nj][0] + bv.x) * sc; o0.y = (d[mi][nj][1] + bv.y) * sc;
            o1.x = (d[mi][nj][2] + bv.x) * sc; o1.y = (d[mi][nj][3] + bv.y) * sc;
            *(float2*)(g_qkv + (size_t)row * 384 + col) = o0;
            *(float2*)(g_qkv + (size_t)(row + 8) * 384 + col) = o1;
        }
    }
}

// ---------------------------------------------------------------------------
// Kernel 2: single-pass flash attention. Block = (win, head), 512 thr, 1 sync.
// Smem: Ks[392][36] | Vt[32][396] | rid[392]  (~107.5 KB -> 2 blocks/SM)
// Q A-fragments loaded directly from gmem per tile.
// ---------------------------------------------------------------------------
__global__ __launch_bounds__(512, 2) void attn_kernel(const float* __restrict__ rpb)
{
    extern __shared__ float sm[];
    float* Ks = sm;                      // 392*36 = 14112
    float* Vt = Ks + 14112;              // 32*396 = 12672
    unsigned char* rid = (unsigned char*)(Vt + 12672);

    int bx = blockIdx.x;
    int win = bx >> 2, head = bx & 3;
    int tid = threadIdx.x;

    const float* qbase = g_qkv + (size_t)win * (392 * 384) + head * 32;
    const float* kbase = qbase + 128;
    const float* vbase = qbase + 256;

    // region ids for shift mask
    int w2 = win & 127;
    int bt = ((w2 >> 6) == 1), bh = (((w2 >> 3) & 7) == 7), bw = ((w2 & 7) == 7);
    for (int l = tid; l < 392; l += 512) {
        int lt = l / 49; int r = l - lt * 49; int lh = r / 7; int lw = r - lh * 7;
        int rt = bt ? ((lt < 4) ? 1 : 2) : 0;
        int rh = bh ? ((lh < 4) ? 1 : 2) : 0;
        int rw = bw ? ((lw < 4) ? 1 : 2) : 0;
        rid[l] = (unsigned char)(rt * 9 + rh * 3 + rw);
    }
    // K rows (float4, tf32)
    for (int i = tid; i < 392 * 8; i += 512) {
        int j = i >> 3, c4 = i & 7;
        float4 v = *(const float4*)(kbase + (size_t)j * 384 + c4 * 4);
        float* d = Ks + j * 36 + c4 * 4;
        d[0] = u2f(rna(v.x)); d[1] = u2f(rna(v.y));
        d[2] = u2f(rna(v.z)); d[3] = u2f(rna(v.w));
    }
    // V transposed
    for (int i = tid; i < 392 * 32; i += 512) {
        int j = i >> 5, c = i & 31;
        Vt[c * 396 + j] = u2f(rna(vbase[(size_t)j * 384 + c]));
    }
    __syncthreads();   // the only block-wide sync

    int lane = tid & 31, warp = tid >> 5;
    const float* bhp = rpb + (size_t)head * (392 * 392);

    unsigned ksb = sptr(Ks + (lane & 7) * 36 + ((lane >> 3) & 1) * 4);
    unsigned vtb = sptr(Vt + (lane & 7) * 396 + ((lane >> 3) & 1) * 4);
    int qsrc1 = (lane & ~3) | ((lane & 3) >> 1);
    int qsrc2 = qsrc1 + 2;
    bool odd = (lane & 1);

    for (int mt = warp; mt < 25; mt += 16) {
        int q0m = mt * 16;
        int qr = q0m + (lane >> 2);
        int qc0 = (qr < 392) ? qr : 391;
        int qc1 = (qr + 8 < 392) ? (qr + 8) : 391;

        // A fragments directly from gmem (k = 0..31)
        unsigned a[4][4];
        {
            const float* q0p = qbase + (size_t)qc0 * 384 + (lane & 3);
            const float* q1p = qbase + (size_t)qc1 * 384 + (lane & 3);
            #pragma unroll
            for (int ks = 0; ks < 4; ks++) {
                a[ks][0] = rna(__ldg(q0p + ks * 8));
                a[ks][1] = rna(__ldg(q1p + ks * 8));
                a[ks][2] = rna(__ldg(q0p + ks * 8 + 4));
                a[ks][3] = rna(__ldg(q1p + ks * 8 + 4));
            }
        }

        unsigned char rq0 = rid[qc0], rq1 = rid[qc1];
        const float* br0 = bhp + (size_t)qc0 * 392;
        const float* br1 = bhp + (size_t)qc1 * 392;

        float oacc[4][4];
        #pragma unroll
        for (int dt = 0; dt < 4; dt++)
            #pragma unroll
            for (int r = 0; r < 4; r++) oacc[dt][r] = 0.f;
        float rs0 = 0.f, rs1 = 0.f;

        #pragma unroll 2
        for (int jt = 0; jt < 49; jt++) {
            // S = Q K^T (16x8)
            float s[4] = {0.f, 0.f, 0.f, 0.f};
            unsigned kb = ksb + (unsigned)jt * 1152;
            #pragma unroll
            for (int ks = 0; ks < 4; ks++) {
                unsigned b[2];
                ldsm2(b, kb + ks * 32);
                mma8(s, a[ks], b);
            }
            // bias + mask + exp
            int jc = jt * 8 + 2 * (lane & 3);
            unsigned char rj0 = rid[jc], rj1 = rid[jc + 1];
            float2 b0 = *(const float2*)(br0 + jc);
            float2 b1 = *(const float2*)(br1 + jc);
            float e0 = (rq0 == rj0) ? u2f(rna(__expf(s[0] + b0.x))) : 0.f;
            float e1 = (rq0 == rj1) ? u2f(rna(__expf(s[1] + b0.y))) : 0.f;
            float e2 = (rq1 == rj0) ? u2f(rna(__expf(s[2] + b1.x))) : 0.f;
            float e3 = (rq1 == rj1) ? u2f(rna(__expf(s[3] + b1.y))) : 0.f;
            rs0 += e0 + e1;
            rs1 += e2 + e3;
            // relayout C-frag -> A-frag
            float t00 = __shfl_sync(0xffffffffu, e0, qsrc1);
            float t01 = __shfl_sync(0xffffffffu, e1, qsrc1);
            float t10 = __shfl_sync(0xffffffffu, e2, qsrc1);
            float t11 = __shfl_sync(0xffffffffu, e3, qsrc1);
            float u00 = __shfl_sync(0xffffffffu, e0, qsrc2);
            float u01 = __shfl_sync(0xffffffffu, e1, qsrc2);
            float u10 = __shfl_sync(0xffffffffu, e2, qsrc2);
            float u11 = __shfl_sync(0xffffffffu, e3, qsrc2);
            unsigned pa[4];
            pa[0] = f2u(odd ? t01 : t00);
            pa[1] = f2u(odd ? t11 : t10);
            pa[2] = f2u(odd ? u01 : u00);
            pa[3] = f2u(odd ? u11 : u10);
            // PV: P(16x8) x V(8x32)
            unsigned vb0 = vtb + (unsigned)jt * 32;
            #pragma unroll
            for (int dt = 0; dt < 4; dt++) {
                unsigned b[2];
                ldsm2(b, vb0 + (unsigned)dt * 12672);
                mma8(oacc[dt], pa, b);
            }
        }

        rs0 += __shfl_xor_sync(0xffffffffu, rs0, 1);
        rs0 += __shfl_xor_sync(0xffffffffu, rs0, 2);
        rs1 += __shfl_xor_sync(0xffffffffu, rs1, 1);
        rs1 += __shfl_xor_sync(0xffffffffu, rs1, 2);
        float si0 = 1.f / rs0, si1 = 1.f / rs1;

        size_t ob = ((size_t)win * 392 + qr) * 128 + head * 32;
        #pragma unroll
        for (int dt = 0; dt < 4; dt++) {
            int dc = dt * 8 + 2 * (lane & 3);
            float2 o0; o0.x = oacc[dt][0] * si0; o0.y = oacc[dt][1] * si0;
            *(float2*)(g_att + ob + dc) = o0;
            if (qr + 8 < 392) {
                float2 o1; o1.x = oacc[dt][2] * si1; o1.y = oacc[dt][3] * si1;
                *(float2*)(g_att + ob + 8 * 128 + dc) = o1;
            }
        }
    }
}

// ---------------------------------------------------------------------------
// Kernel 3: proj GEMM (1xTF32), fused scatter.
// ---------------------------------------------------------------------------
__global__ __launch_bounds__(512, 2) void proj_kernel(
    const float* __restrict__ w, const float* __restrict__ bias,
    float* __restrict__ out)
{
    extern __shared__ float sm[];
    float* As = sm;
    float* Bs = As + 4608;
    int* rowdst = (int*)(Bs + 4608);

    int m0 = blockIdx.x * 128;
    int tid = threadIdx.x;
    if (tid < 128) rowdst[tid] = token_img_offset(m0 + tid);
    __syncthreads();

    int lane = tid & 31, warp = tid >> 5;
    int wm = warp >> 2, wn = warp & 3;

    float d[2][4][4];
    #pragma unroll
    for (int mi = 0; mi < 2; mi++)
        #pragma unroll
        for (int nj = 0; nj < 4; nj++)
            #pragma unroll
            for (int r = 0; r < 4; r++) d[mi][nj][r] = 0.f;

    for (int kc = 0; kc < 4; kc++) {
        #pragma unroll
        for (int it = 0; it < 2; it++) {
            int idx = tid + it * 512;
            int r = idx >> 3, f4 = idx & 7;
            float4 va = *(const float4*)(g_att + (size_t)(m0 + r) * 128 + kc * 32 + f4 * 4);
            float* ad = As + r * 36 + f4 * 4;
            ad[0] = u2f(rna(va.x)); ad[1] = u2f(rna(va.y));
            ad[2] = u2f(rna(va.z)); ad[3] = u2f(rna(va.w));
            float4 vb = *(const float4*)(w + (size_t)r * 128 + kc * 32 + f4 * 4);
            float* bd = Bs + r * 36 + f4 * 4;
            bd[0] = u2f(rna(vb.x)); bd[1] = u2f(rna(vb.y));
            bd[2] = u2f(rna(vb.z)); bd[3] = u2f(rna(vb.w));
        }
        __syncthreads();
        gemm1_core(As, Bs, lane, wm, wn, d);
        __syncthreads();
    }

    #pragma unroll
    for (int mi = 0; mi < 2; mi++) {
        int ml = wm * 32 + mi * 16 + (lane >> 2);
        #pragma unroll
        for (int nj = 0; nj < 4; nj++) {
            int col = wn * 32 + nj * 8 + (lane & 3) * 2;
            float2 bv = *(const float2*)(bias + col);
            float2 o0, o1;
            o0.x = d[mi][nj][0] + bv.x; o0.y = d[mi][nj][1] + bv.y;
            o1.x = d[mi][nj][2] + bv.x; o1.y = d[mi][nj][3] + bv.y;
            *(float2*)(out + rowdst[ml] + col) = o0;
            *(float2*)(out + rowdst[ml + 8] + col) = o1;
        }
    }
}

// ---------------------------------------------------------------------------
extern "C" void kernel_launch(void* const* d_in, const int* in_sizes, int n_in,
                              void* d_out, int out_size)
{
    const float* x   = (const float*)d_in[0];
    const float* qw  = (const float*)d_in[1];
    const float* qb  = (const float*)d_in[2];
    const float* pw  = (const float*)d_in[3];
    const float* pb  = (const float*)d_in[4];
    const float* rpb = (const float*)d_in[5];
    float* out = (float*)d_out;

    const int smemG = 2 * 4608 * 4 + 128 * 4;        // 37,376 B
    const int smemA = (14112 + 12672) * 4 + 392 + 8; // 107,536 B

    cudaFuncSetAttribute(qkv_kernel,  cudaFuncAttributeMaxDynamicSharedMemorySize, smemG);
    cudaFuncSetAttribute(attn_kernel, cudaFuncAttributeMaxDynamicSharedMemorySize, smemA);
    cudaFuncSetAttribute(proj_kernel, cudaFuncAttributeMaxDynamicSharedMemorySize, smemG);

    qkv_kernel<<<dim3(3, 784), 512, smemG>>>(x, qw, qb);
    attn_kernel<<<1024, 512, smemA>>>(rpb);
    proj_kernel<<<784, 512, smemG>>>(pw, pb, out);
}

// round 9
// speedup vs baseline: 2.4202x; 1.2956x over previous
#include <cuda_runtime.h>

#define TOKENS 100352   // 256 windows * 392 tokens

__device__ float  g_qkv[(size_t)TOKENS * 384];   // [token][384]: q*scale | k | v
__device__ float  g_att[(size_t)TOKENS * 128];   // attention out, token-major
__device__ float4 g_rpbT[4 * 25 * 49 * 32];      // frag-ordered rel-pos bias

__device__ __forceinline__ float u2f(unsigned u) { return __uint_as_float(u); }
__device__ __forceinline__ unsigned f2u(float f) { return __float_as_uint(f); }
__device__ __forceinline__ void mma8(float* d, const unsigned* a, const unsigned* b) {
    asm volatile("mma.sync.aligned.m16n8k8.row.col.f32.tf32.tf32.f32 "
        "{%0,%1,%2,%3}, {%4,%5,%6,%7}, {%8,%9}, {%0,%1,%2,%3};"
        : "+f"(d[0]), "+f"(d[1]), "+f"(d[2]), "+f"(d[3])
        : "r"(a[0]), "r"(a[1]), "r"(a[2]), "r"(a[3]), "r"(b[0]), "r"(b[1]));
}
__device__ __forceinline__ void ldsm4(unsigned* r, unsigned a) {
    asm volatile("ldmatrix.sync.aligned.m8n8.x4.shared.b16 {%0,%1,%2,%3},[%4];"
        : "=r"(r[0]), "=r"(r[1]), "=r"(r[2]), "=r"(r[3]) : "r"(a));
}
__device__ __forceinline__ unsigned sptr(const void* p) {
    return (unsigned)__cvta_generic_to_shared(p);
}
__device__ __forceinline__ void cpa16(unsigned dst, const float* src) {
    asm volatile("cp.async.cg.shared.global [%0],[%1],16;" :: "r"(dst), "l"(src));
}

// token -> element offset in [B,T,H,W,C] with cyclic shift (+4,+3,+3)
__device__ __forceinline__ int token_img_offset(int m) {
    int win = m / 392;
    int l   = m - win * 392;
    int b   = win >> 7;
    int w2  = win & 127;
    int it  = w2 >> 6, ih = (w2 >> 3) & 7, iw = w2 & 7;
    int lt  = l / 49; int r = l - lt * 49;
    int lh  = r / 7;  int lw = r - lh * 7;
    int t = (it * 8 + lt + 4) & 15;
    int h = ih * 7 + lh + 3; if (h >= 56) h -= 56;
    int w = iw * 7 + lw + 3; if (w >= 56) w -= 56;
    return (((b * 16 + t) * 56 + h) * 56 + w) * 128;
}

// ---------------------------------------------------------------------------
// Kernel 0: pre-pack rpb into fragment order. 156800 threads.
// ---------------------------------------------------------------------------
__global__ __launch_bounds__(256) void prep_kernel(const float* __restrict__ rpb)
{
    int i = blockIdx.x * 256 + threadIdx.x;
    if (i >= 4 * 25 * 49 * 32) return;
    int lane = i & 31; int t = i >> 5;
    int jt = t % 49; t /= 49;
    int mt = t % 25; int h = t / 25;
    int qr = mt * 16 + (lane >> 2);
    int qc0 = (qr < 392) ? qr : 391;
    int qc1 = (qr + 8 < 392) ? qr + 8 : 391;
    int jc = jt * 8 + 2 * (lane & 3);
    const float* bp = rpb + (size_t)h * (392 * 392);
    float4 v;
    v.x = bp[(size_t)qc0 * 392 + jc];
    v.y = bp[(size_t)qc0 * 392 + jc + 1];
    v.z = bp[(size_t)qc1 * 392 + jc];
    v.w = bp[(size_t)qc1 * 392 + jc + 1];
    g_rpbT[i] = v;
}

// ---------------------------------------------------------------------------
// 1xTF32 GEMM core (raw-truncation operands): 128x128 tile, 512 thr.
// ---------------------------------------------------------------------------
__device__ __forceinline__ void gemm1_core(
    float* As, float* Bs, int lane, int wm, int wn, float d[2][4][4])
{
    unsigned aoff = sptr(As + (wm * 32 + ((lane >> 3) & 1) * 8 + (lane & 7)) * 36
                            + ((lane >> 4) & 1) * 4);
    unsigned boff = sptr(Bs + (wn * 32 + ((lane >> 4) & 1) * 8 + (lane & 7)) * 36
                            + ((lane >> 3) & 1) * 4);
    const unsigned R16 = 16 * 36 * 4;

    #pragma unroll
    for (int ks = 0; ks < 4; ks++) {
        unsigned ka = ks * 32;
        unsigned a[2][4], b[2][4];
        ldsm4(a[0], aoff + ka);  ldsm4(a[1], aoff + ka + R16);
        ldsm4(b[0], boff + ka);  ldsm4(b[1], boff + ka + R16);
        #pragma unroll
        for (int mi = 0; mi < 2; mi++)
            #pragma unroll
            for (int p = 0; p < 2; p++) {
                mma8(d[mi][2 * p],     a[mi], b[p]);
                mma8(d[mi][2 * p + 1], a[mi], b[p] + 2);
            }
    }
}

// ---------------------------------------------------------------------------
// Kernel 1: QKV GEMM, cp.async double-buffered, fused gather. grid (3, 784).
// ---------------------------------------------------------------------------
__global__ __launch_bounds__(512, 2) void qkv_kernel(
    const float* __restrict__ x, const float* __restrict__ w,
    const float* __restrict__ bias)
{
    extern __shared__ float sm[];
    float* Abuf = sm;                 // [2][128*36]
    float* Bbuf = sm + 2 * 4608;      // [2][128*36]
    int* rowsrc = (int*)(sm + 4 * 4608);

    int m0 = blockIdx.y * 128, n0 = blockIdx.x * 128;
    int tid = threadIdx.x;
    if (tid < 128) rowsrc[tid] = token_img_offset(m0 + tid);
    __syncthreads();

    int lane = tid & 31, warp = tid >> 5;
    int wm = warp >> 2, wn = warp & 3;

    float d[2][4][4];
    #pragma unroll
    for (int mi = 0; mi < 2; mi++)
        #pragma unroll
        for (int nj = 0; nj < 4; nj++)
            #pragma unroll
            for (int r = 0; r < 4; r++) d[mi][nj][r] = 0.f;

    int r0 = tid >> 3, f40 = (tid & 7) * 4;
    int r1 = (tid + 512) >> 3;

    // issue kc=0 into buf 0
    {
        cpa16(sptr(Abuf + r0 * 36 + f40), x + rowsrc[r0] + f40);
        cpa16(sptr(Bbuf + r0 * 36 + f40), w + (size_t)(n0 + r0) * 128 + f40);
        cpa16(sptr(Abuf + r1 * 36 + f40), x + rowsrc[r1] + f40);
        cpa16(sptr(Bbuf + r1 * 36 + f40), w + (size_t)(n0 + r1) * 128 + f40);
        asm volatile("cp.async.commit_group;");
    }
    #pragma unroll
    for (int kc = 0; kc < 4; kc++) {
        if (kc < 3) {
            int bi = (kc + 1) & 1, kof = (kc + 1) * 32;
            cpa16(sptr(Abuf + bi * 4608 + r0 * 36 + f40), x + rowsrc[r0] + kof + f40);
            cpa16(sptr(Bbuf + bi * 4608 + r0 * 36 + f40), w + (size_t)(n0 + r0) * 128 + kof + f40);
            cpa16(sptr(Abuf + bi * 4608 + r1 * 36 + f40), x + rowsrc[r1] + kof + f40);
            cpa16(sptr(Bbuf + bi * 4608 + r1 * 36 + f40), w + (size_t)(n0 + r1) * 128 + kof + f40);
            asm volatile("cp.async.commit_group;");
            asm volatile("cp.async.wait_group 1;");
        } else {
            asm volatile("cp.async.wait_group 0;");
        }
        __syncthreads();
        gemm1_core(Abuf + (kc & 1) * 4608, Bbuf + (kc & 1) * 4608, lane, wm, wn, d);
        __syncthreads();
    }

    #pragma unroll
    for (int mi = 0; mi < 2; mi++) {
        int row = m0 + wm * 32 + mi * 16 + (lane >> 2);
        #pragma unroll
        for (int nj = 0; nj < 4; nj++) {
            int col = n0 + wn * 32 + nj * 8 + (lane & 3) * 2;
            float sc = (col < 128) ? 0.17677669529663687f : 1.0f;
            float2 bv = *(const float2*)(bias + col);
            float2 o0, o1;
            o0.x = (d[mi][nj][0] + bv.x) * sc; o0.y = (d[mi][nj][1] + bv.y) * sc;
            o1.x = (d[mi][nj][2] + bv.x) * sc; o1.y = (d[mi][nj][3] + bv.y) * sc;
            *(float2*)(g_qkv + (size_t)row * 384 + col) = o0;
            *(float2*)(g_qkv + (size_t)(row + 8) * 384 + col) = o1;
        }
    }
}

// ---------------------------------------------------------------------------
// Kernel 2: single-pass flash attention. Block = (win, head), 512 thr, 1 sync.
// Smem: Ks[392][36] | Vt[32][396] | rid[392]  (~107.5 KB -> 2 blocks/SM)
// ---------------------------------------------------------------------------
__global__ __launch_bounds__(512, 2) void attn_kernel()
{
    extern __shared__ float sm[];
    float* Ks = sm;                      // 392*36 = 14112
    float* Vt = Ks + 14112;              // 32*396 = 12672
    unsigned char* rid = (unsigned char*)(Vt + 12672);

    int bx = blockIdx.x;
    int win = bx >> 2, head = bx & 3;
    int tid = threadIdx.x;

    const float* qbase = g_qkv + (size_t)win * (392 * 384) + head * 32;
    const float* kbase = qbase + 128;
    const float* vbase = qbase + 256;

    // region ids for shift mask
    int w2 = win & 127;
    int bt = ((w2 >> 6) == 1), bh = (((w2 >> 3) & 7) == 7), bw = ((w2 & 7) == 7);
    for (int l = tid; l < 392; l += 512) {
        int lt = l / 49; int r = l - lt * 49; int lh = r / 7; int lw = r - lh * 7;
        int rt = bt ? ((lt < 4) ? 1 : 2) : 0;
        int rh = bh ? ((lh < 4) ? 1 : 2) : 0;
        int rw = bw ? ((lw < 4) ? 1 : 2) : 0;
        rid[l] = (unsigned char)(rt * 9 + rh * 3 + rw);
    }
    // K rows raw fp32 (HW truncates to tf32 in mma)
    for (int i = tid; i < 392 * 8; i += 512) {
        int j = i >> 3, c4 = i & 7;
        float4 v = *(const float4*)(kbase + (size_t)j * 384 + c4 * 4);
        *(float4*)(Ks + j * 36 + c4 * 4) = v;
    }
    // V transposed
    for (int i = tid; i < 392 * 32; i += 512) {
        int j = i >> 5, c = i & 31;
        Vt[c * 396 + j] = vbase[(size_t)j * 384 + c];
    }
    __syncthreads();   // the only block-wide sync

    int lane = tid & 31, warp = tid >> 5;

    // ldsm4 bases: K covers ks-groups, V covers dt-pairs
    unsigned ksb4 = sptr(Ks + (lane & 7) * 36 + ((lane >> 3) & 3) * 4);
    unsigned vtb4 = sptr(Vt + (((lane >> 4) & 1) * 8 + (lane & 7)) * 396
                            + ((lane >> 3) & 1) * 4);
    int qsrc1 = (lane & ~3) | ((lane & 3) >> 1);
    int qsrc2 = qsrc1 + 2;
    bool odd = (lane & 1);

    for (int mt = warp; mt < 25; mt += 16) {
        int q0m = mt * 16;
        int qr = q0m + (lane >> 2);
        int qc0 = (qr < 392) ? qr : 391;
        int qc1 = (qr + 8 < 392) ? (qr + 8) : 391;

        // A fragments directly from gmem (raw bits)
        unsigned a[4][4];
        {
            const unsigned* q0p = (const unsigned*)(qbase + (size_t)qc0 * 384) + (lane & 3);
            const unsigned* q1p = (const unsigned*)(qbase + (size_t)qc1 * 384) + (lane & 3);
            #pragma unroll
            for (int ks = 0; ks < 4; ks++) {
                a[ks][0] = __ldg(q0p + ks * 8);
                a[ks][1] = __ldg(q1p + ks * 8);
                a[ks][2] = __ldg(q0p + ks * 8 + 4);
                a[ks][3] = __ldg(q1p + ks * 8 + 4);
            }
        }

        unsigned char rq0 = rid[qc0], rq1 = rid[qc1];
        const float4* bbase = g_rpbT + ((head * 25 + mt) * 49) * 32 + lane;

        float oacc[4][4];
        #pragma unroll
        for (int dt = 0; dt < 4; dt++)
            #pragma unroll
            for (int r = 0; r < 4; r++) oacc[dt][r] = 0.f;
        float rs0 = 0.f, rs1 = 0.f;

        float4 bv = __ldg(bbase);   // jt=0 bias

        #pragma unroll 2
        for (int jt = 0; jt < 49; jt++) {
            float4 bv_next;
            if (jt < 48) bv_next = __ldg(bbase + (jt + 1) * 32);
            // S = Q K^T (16x8)
            float s[4] = {0.f, 0.f, 0.f, 0.f};
            unsigned kb = ksb4 + (unsigned)jt * 1152;
            unsigned bk0[4], bk1[4];
            ldsm4(bk0, kb);
            ldsm4(bk1, kb + 64);
            mma8(s, a[0], bk0);
            mma8(s, a[1], bk0 + 2);
            mma8(s, a[2], bk1);
            mma8(s, a[3], bk1 + 2);
            // bias + mask + exp
            int jc = jt * 8 + 2 * (lane & 3);
            unsigned char rj0 = rid[jc], rj1 = rid[jc + 1];
            float e0 = (rq0 == rj0) ? __expf(s[0] + bv.x) : 0.f;
            float e1 = (rq0 == rj1) ? __expf(s[1] + bv.y) : 0.f;
            float e2 = (rq1 == rj0) ? __expf(s[2] + bv.z) : 0.f;
            float e3 = (rq1 == rj1) ? __expf(s[3] + bv.w) : 0.f;
            rs0 += e0 + e1;
            rs1 += e2 + e3;
            // relayout C-frag -> A-frag
            float t00 = __shfl_sync(0xffffffffu, e0, qsrc1);
            float t01 = __shfl_sync(0xffffffffu, e1, qsrc1);
            float t10 = __shfl_sync(0xffffffffu, e2, qsrc1);
            float t11 = __shfl_sync(0xffffffffu, e3, qsrc1);
            float u00 = __shfl_sync(0xffffffffu, e0, qsrc2);
            float u01 = __shfl_sync(0xffffffffu, e1, qsrc2);
            float u10 = __shfl_sync(0xffffffffu, e2, qsrc2);
            float u11 = __shfl_sync(0xffffffffu, e3, qsrc2);
            unsigned pa[4];
            pa[0] = f2u(odd ? t01 : t00);
            pa[1] = f2u(odd ? t11 : t10);
            pa[2] = f2u(odd ? u01 : u00);
            pa[3] = f2u(odd ? u11 : u10);
            // PV: P(16x8) x V(8x32) via 2 ldsm4 (dt pairs)
            unsigned vb = vtb4 + (unsigned)jt * 32;
            unsigned bv0[4], bv1[4];
            ldsm4(bv0, vb);
            ldsm4(bv1, vb + 25344);
            mma8(oacc[0], pa, bv0);
            mma8(oacc[1], pa, bv0 + 2);
            mma8(oacc[2], pa, bv1);
            mma8(oacc[3], pa, bv1 + 2);
            bv = bv_next;
        }

        rs0 += __shfl_xor_sync(0xffffffffu, rs0, 1);
        rs0 += __shfl_xor_sync(0xffffffffu, rs0, 2);
        rs1 += __shfl_xor_sync(0xffffffffu, rs1, 1);
        rs1 += __shfl_xor_sync(0xffffffffu, rs1, 2);
        float si0 = 1.f / rs0, si1 = 1.f / rs1;

        size_t ob = ((size_t)win * 392 + qr) * 128 + head * 32;
        #pragma unroll
        for (int dt = 0; dt < 4; dt++) {
            int dc = dt * 8 + 2 * (lane & 3);
            float2 o0; o0.x = oacc[dt][0] * si0; o0.y = oacc[dt][1] * si0;
            *(float2*)(g_att + ob + dc) = o0;
            if (qr + 8 < 392) {
                float2 o1; o1.x = oacc[dt][2] * si1; o1.y = oacc[dt][3] * si1;
                *(float2*)(g_att + ob + 8 * 128 + dc) = o1;
            }
        }
    }
}

// ---------------------------------------------------------------------------
// Kernel 3: proj GEMM, cp.async double-buffered, fused scatter.
// ---------------------------------------------------------------------------
__global__ __launch_bounds__(512, 2) void proj_kernel(
    const float* __restrict__ w, const float* __restrict__ bias,
    float* __restrict__ out)
{
    extern __shared__ float sm[];
    float* Abuf = sm;
    float* Bbuf = sm + 2 * 4608;
    int* rowdst = (int*)(sm + 4 * 4608);

    int m0 = blockIdx.x * 128;
    int tid = threadIdx.x;
    if (tid < 128) rowdst[tid] = token_img_offset(m0 + tid);
    __syncthreads();

    int lane = tid & 31, warp = tid >> 5;
    int wm = warp >> 2, wn = warp & 3;

    float d[2][4][4];
    #pragma unroll
    for (int mi = 0; mi < 2; mi++)
        #pragma unroll
        for (int nj = 0; nj < 4; nj++)
            #pragma unroll
            for (int r = 0; r < 4; r++) d[mi][nj][r] = 0.f;

    int r0 = tid >> 3, f40 = (tid & 7) * 4;
    int r1 = (tid + 512) >> 3;

    {
        cpa16(sptr(Abuf + r0 * 36 + f40), g_att + (size_t)(m0 + r0) * 128 + f40);
        cpa16(sptr(Bbuf + r0 * 36 + f40), w + (size_t)r0 * 128 + f40);
        cpa16(sptr(Abuf + r1 * 36 + f40), g_att + (size_t)(m0 + r1) * 128 + f40);
        cpa16(sptr(Bbuf + r1 * 36 + f40), w + (size_t)r1 * 128 + f40);
        asm volatile("cp.async.commit_group;");
    }
    #pragma unroll
    for (int kc = 0; kc < 4; kc++) {
        if (kc < 3) {
            int bi = (kc + 1) & 1, kof = (kc + 1) * 32;
            cpa16(sptr(Abuf + bi * 4608 + r0 * 36 + f40), g_att + (size_t)(m0 + r0) * 128 + kof + f40);
            cpa16(sptr(Bbuf + bi * 4608 + r0 * 36 + f40), w + (size_t)r0 * 128 + kof + f40);
            cpa16(sptr(Abuf + bi * 4608 + r1 * 36 + f40), g_att + (size_t)(m0 + r1) * 128 + kof + f40);
            cpa16(sptr(Bbuf + bi * 4608 + r1 * 36 + f40), w + (size_t)r1 * 128 + kof + f40);
            asm volatile("cp.async.commit_group;");
            asm volatile("cp.async.wait_group 1;");
        } else {
            asm volatile("cp.async.wait_group 0;");
        }
        __syncthreads();
        gemm1_core(Abuf + (kc & 1) * 4608, Bbuf + (kc & 1) * 4608, lane, wm, wn, d);
        __syncthreads();
    }

    #pragma unroll
    for (int mi = 0; mi < 2; mi++) {
        int ml = wm * 32 + mi * 16 + (lane >> 2);
        #pragma unroll
        for (int nj = 0; nj < 4; nj++) {
            int col = wn * 32 + nj * 8 + (lane & 3) * 2;
            float2 bvv = *(const float2*)(bias + col);
            float2 o0, o1;
            o0.x = d[mi][nj][0] + bvv.x; o0.y = d[mi][nj][1] + bvv.y;
            o1.x = d[mi][nj][2] + bvv.x; o1.y = d[mi][nj][3] + bvv.y;
            *(float2*)(out + rowdst[ml] + col) = o0;
            *(float2*)(out + rowdst[ml + 8] + col) = o1;
        }
    }
}

// ---------------------------------------------------------------------------
extern "C" void kernel_launch(void* const* d_in, const int* in_sizes, int n_in,
                              void* d_out, int out_size)
{
    const float* x   = (const float*)d_in[0];
    const float* qw  = (const float*)d_in[1];
    const float* qb  = (const float*)d_in[2];
    const float* pw  = (const float*)d_in[3];
    const float* pb  = (const float*)d_in[4];
    const float* rpb = (const float*)d_in[5];
    float* out = (float*)d_out;

    const int smemG = 4 * 4608 * 4 + 512;            // 74,240 B
    const int smemA = (14112 + 12672) * 4 + 392 + 8; // 107,536 B

    cudaFuncSetAttribute(qkv_kernel,  cudaFuncAttributeMaxDynamicSharedMemorySize, smemG);
    cudaFuncSetAttribute(attn_kernel, cudaFuncAttributeMaxDynamicSharedMemorySize, smemA);
    cudaFuncSetAttribute(proj_kernel, cudaFuncAttributeMaxDynamicSharedMemorySize, smemG);

    prep_kernel<<<613, 256>>>(rpb);
    qkv_kernel<<<dim3(3, 784), 512, smemG>>>(x, qw, qb);
    attn_kernel<<<1024, 512, smemA>>>();
    proj_kernel<<<784, 512, smemG>>>(pw, pb, out);
}

// round 10
// speedup vs baseline: 2.6622x; 1.1000x over previous
#include <cuda_runtime.h>

#define TOKENS 100352   // 256 windows * 392 tokens

__device__ float  g_qkv[(size_t)TOKENS * 384];   // [token][384]: q*scale*log2e | k | v
__device__ float  g_att[(size_t)TOKENS * 128];   // attention out, token-major
__device__ float4 g_rpbT[4 * 25 * 49 * 32];      // frag-ordered rel-pos bias * log2e
__device__ float  g_qwr[384 * 128];              // rna-rounded qkv weight
__device__ float  g_pwr[128 * 128];              // rna-rounded proj weight

__device__ __forceinline__ unsigned rna(float f) {
    unsigned u; asm("cvt.rna.tf32.f32 %0, %1;" : "=r"(u) : "f"(f)); return u;
}
__device__ __forceinline__ float u2f(unsigned u) { return __uint_as_float(u); }
__device__ __forceinline__ float ex2(float x) {
    float r; asm("ex2.approx.ftz.f32 %0, %1;" : "=f"(r) : "f"(x)); return r;
}
__device__ __forceinline__ void mma8(float* d, const unsigned* a, const unsigned* b) {
    asm volatile("mma.sync.aligned.m16n8k8.row.col.f32.tf32.tf32.f32 "
        "{%0,%1,%2,%3}, {%4,%5,%6,%7}, {%8,%9}, {%0,%1,%2,%3};"
        : "+f"(d[0]), "+f"(d[1]), "+f"(d[2]), "+f"(d[3])
        : "r"(a[0]), "r"(a[1]), "r"(a[2]), "r"(a[3]), "r"(b[0]), "r"(b[1]));
}
__device__ __forceinline__ void ldsm4(unsigned* r, unsigned a) {
    asm volatile("ldmatrix.sync.aligned.m8n8.x4.shared.b16 {%0,%1,%2,%3},[%4];"
        : "=r"(r[0]), "=r"(r[1]), "=r"(r[2]), "=r"(r[3]) : "r"(a));
}
__device__ __forceinline__ unsigned sptr(const void* p) {
    return (unsigned)__cvta_generic_to_shared(p);
}
__device__ __forceinline__ void cpa16(unsigned dst, const float* src) {
    asm volatile("cp.async.cg.shared.global [%0],[%1],16;" :: "r"(dst), "l"(src));
}

// token -> element offset in [B,T,H,W,C] with cyclic shift (+4,+3,+3)
__device__ __forceinline__ int token_img_offset(int m) {
    int win = m / 392;
    int l   = m - win * 392;
    int b   = win >> 7;
    int w2  = win & 127;
    int it  = w2 >> 6, ih = (w2 >> 3) & 7, iw = w2 & 7;
    int lt  = l / 49; int r = l - lt * 49;
    int lh  = r / 7;  int lw = r - lh * 7;
    int t = (it * 8 + lt + 4) & 15;
    int h = ih * 7 + lh + 3; if (h >= 56) h -= 56;
    int w = iw * 7 + lw + 3; if (w >= 56) w -= 56;
    return (((b * 16 + t) * 56 + h) * 56 + w) * 128;
}

// ---------------------------------------------------------------------------
// Kernel 0: pre-pack bias (frag order, *log2e) + rna-rounded weights.
// ---------------------------------------------------------------------------
__global__ __launch_bounds__(256) void prep_kernel(
    const float* __restrict__ rpb, const float* __restrict__ qw,
    const float* __restrict__ pw)
{
    int i = blockIdx.x * 256 + threadIdx.x;
    const int NB = 4 * 25 * 49 * 32;          // 156800
    if (i < NB) {
        int lane = i & 31; int t = i >> 5;
        int jt = t % 49; t /= 49;
        int mt = t % 25; int h = t / 25;
        int qr = mt * 16 + (lane >> 2);
        int qc0 = (qr < 392) ? qr : 391;
        int qc1 = (qr + 8 < 392) ? qr + 8 : 391;
        int jc = jt * 8 + 2 * (lane & 3);
        const float* bp = rpb + (size_t)h * (392 * 392);
        const float L2E = 1.4426950408889634f;
        float4 v;
        v.x = bp[(size_t)qc0 * 392 + jc] * L2E;
        v.y = bp[(size_t)qc0 * 392 + jc + 1] * L2E;
        v.z = bp[(size_t)qc1 * 392 + jc] * L2E;
        v.w = bp[(size_t)qc1 * 392 + jc + 1] * L2E;
        g_rpbT[i] = v;
    } else if (i < NB + 384 * 128) {
        int k = i - NB;
        g_qwr[k] = u2f(rna(qw[k]));
    } else if (i < NB + 384 * 128 + 128 * 128) {
        int k = i - NB - 384 * 128;
        g_pwr[k] = u2f(rna(pw[k]));
    }
}

// ---------------------------------------------------------------------------
// 1xTF32 GEMM core: 128x128 tile, 512 thr, LDSM operands.
// ---------------------------------------------------------------------------
__device__ __forceinline__ void gemm1_core(
    float* As, float* Bs, int lane, int wm, int wn, float d[2][4][4])
{
    unsigned aoff = sptr(As + (wm * 32 + ((lane >> 3) & 1) * 8 + (lane & 7)) * 36
                            + ((lane >> 4) & 1) * 4);
    unsigned boff = sptr(Bs + (wn * 32 + ((lane >> 4) & 1) * 8 + (lane & 7)) * 36
                            + ((lane >> 3) & 1) * 4);
    const unsigned R16 = 16 * 36 * 4;

    #pragma unroll
    for (int ks = 0; ks < 4; ks++) {
        unsigned ka = ks * 32;
        unsigned a[2][4], b[2][4];
        ldsm4(a[0], aoff + ka);  ldsm4(a[1], aoff + ka + R16);
        ldsm4(b[0], boff + ka);  ldsm4(b[1], boff + ka + R16);
        #pragma unroll
        for (int mi = 0; mi < 2; mi++)
            #pragma unroll
            for (int p = 0; p < 2; p++) {
                mma8(d[mi][2 * p],     a[mi], b[p]);
                mma8(d[mi][2 * p + 1], a[mi], b[p] + 2);
            }
    }
}

// ---------------------------------------------------------------------------
// Kernel 1: QKV GEMM, cp.async double-buffered, fused gather. grid (3, 784).
// q columns scaled by hd^-0.5 * log2e (exp2 softmax domain).
// ---------------------------------------------------------------------------
__global__ __launch_bounds__(512, 2) void qkv_kernel(
    const float* __restrict__ x, const float* __restrict__ bias)
{
    extern __shared__ float sm[];
    float* Abuf = sm;                 // [2][128*36]
    float* Bbuf = sm + 2 * 4608;      // [2][128*36]
    int* rowsrc = (int*)(sm + 4 * 4608);

    int m0 = blockIdx.y * 128, n0 = blockIdx.x * 128;
    int tid = threadIdx.x;
    if (tid < 128) rowsrc[tid] = token_img_offset(m0 + tid);
    __syncthreads();

    int lane = tid & 31, warp = tid >> 5;
    int wm = warp >> 2, wn = warp & 3;

    float d[2][4][4];
    #pragma unroll
    for (int mi = 0; mi < 2; mi++)
        #pragma unroll
        for (int nj = 0; nj < 4; nj++)
            #pragma unroll
            for (int r = 0; r < 4; r++) d[mi][nj][r] = 0.f;

    int r0 = tid >> 3, f40 = (tid & 7) * 4;
    int r1 = (tid + 512) >> 3;

    {
        cpa16(sptr(Abuf + r0 * 36 + f40), x + rowsrc[r0] + f40);
        cpa16(sptr(Bbuf + r0 * 36 + f40), g_qwr + (size_t)(n0 + r0) * 128 + f40);
        cpa16(sptr(Abuf + r1 * 36 + f40), x + rowsrc[r1] + f40);
        cpa16(sptr(Bbuf + r1 * 36 + f40), g_qwr + (size_t)(n0 + r1) * 128 + f40);
        asm volatile("cp.async.commit_group;");
    }
    #pragma unroll
    for (int kc = 0; kc < 4; kc++) {
        if (kc < 3) {
            int bi = (kc + 1) & 1, kof = (kc + 1) * 32;
            cpa16(sptr(Abuf + bi * 4608 + r0 * 36 + f40), x + rowsrc[r0] + kof + f40);
            cpa16(sptr(Bbuf + bi * 4608 + r0 * 36 + f40), g_qwr + (size_t)(n0 + r0) * 128 + kof + f40);
            cpa16(sptr(Abuf + bi * 4608 + r1 * 36 + f40), x + rowsrc[r1] + kof + f40);
            cpa16(sptr(Bbuf + bi * 4608 + r1 * 36 + f40), g_qwr + (size_t)(n0 + r1) * 128 + kof + f40);
            asm volatile("cp.async.commit_group;");
            asm volatile("cp.async.wait_group 1;");
        } else {
            asm volatile("cp.async.wait_group 0;");
        }
        __syncthreads();
        gemm1_core(Abuf + (kc & 1) * 4608, Bbuf + (kc & 1) * 4608, lane, wm, wn, d);
        __syncthreads();
    }

    #pragma unroll
    for (int mi = 0; mi < 2; mi++) {
        int row = m0 + wm * 32 + mi * 16 + (lane >> 2);
        #pragma unroll
        for (int nj = 0; nj < 4; nj++) {
            int col = n0 + wn * 32 + nj * 8 + (lane & 3) * 2;
            float sc = (col < 128) ? 0.25503486f : 1.0f;   // hd^-0.5 * log2e
            float2 bv = *(const float2*)(bias + col);
            float2 o0, o1;
            o0.x = (d[mi][nj][0] + bv.x) * sc; o0.y = (d[mi][nj][1] + bv.y) * sc;
            o1.x = (d[mi][nj][2] + bv.x) * sc; o1.y = (d[mi][nj][3] + bv.y) * sc;
            *(float2*)(g_qkv + (size_t)row * 384 + col) = o0;
            *(float2*)(g_qkv + (size_t)(row + 8) * 384 + col) = o1;
        }
    }
}

// ---------------------------------------------------------------------------
// Attention per-warp core, templated on mask presence.
// ---------------------------------------------------------------------------
template<bool MASKED>
__device__ __forceinline__ void attn_tile(
    int mt, int lane, int win, int head,
    const float* qbase, const unsigned char* rid,
    unsigned ksb4, unsigned vtb4)
{
    int q0m = mt * 16;
    int qr = q0m + (lane >> 2);
    int qc0 = (qr < 392) ? qr : 391;
    int qc1 = (qr + 8 < 392) ? (qr + 8) : 391;

    // A fragments from gmem, rna-rounded
    unsigned a[4][4];
    {
        const float* q0p = qbase + (size_t)qc0 * 384 + (lane & 3);
        const float* q1p = qbase + (size_t)qc1 * 384 + (lane & 3);
        #pragma unroll
        for (int ks = 0; ks < 4; ks++) {
            a[ks][0] = rna(__ldg(q0p + ks * 8));
            a[ks][1] = rna(__ldg(q1p + ks * 8));
            a[ks][2] = rna(__ldg(q0p + ks * 8 + 4));
            a[ks][3] = rna(__ldg(q1p + ks * 8 + 4));
        }
    }

    unsigned char rq0 = 0, rq1 = 0;
    if (MASKED) { rq0 = rid[qc0]; rq1 = rid[qc1]; }
    const float4* bbase = g_rpbT + ((head * 25 + mt) * 49) * 32 + lane;

    float oacc[4][4];
    #pragma unroll
    for (int dt = 0; dt < 4; dt++)
        #pragma unroll
        for (int r = 0; r < 4; r++) oacc[dt][r] = 0.f;
    float rs0 = 0.f, rs1 = 0.f;

    int qsrc1 = (lane & ~3) | ((lane & 3) >> 1);
    int qsrc2 = qsrc1 + 2;
    bool odd = (lane & 1);

    float4 bv = __ldg(bbase);

    #pragma unroll 2
    for (int jt = 0; jt < 49; jt++) {
        float4 bv_next;
        if (jt < 48) bv_next = __ldg(bbase + (jt + 1) * 32);
        // S accumulator initialized with (masked) bias
        float s[4];
        if (MASKED) {
            int jc = jt * 8 + 2 * (lane & 3);
            unsigned char rj0 = rid[jc], rj1 = rid[jc + 1];
            s[0] = (rq0 == rj0) ? bv.x : -1e4f;
            s[1] = (rq0 == rj1) ? bv.y : -1e4f;
            s[2] = (rq1 == rj0) ? bv.z : -1e4f;
            s[3] = (rq1 == rj1) ? bv.w : -1e4f;
        } else {
            s[0] = bv.x; s[1] = bv.y; s[2] = bv.z; s[3] = bv.w;
        }
        unsigned kb = ksb4 + (unsigned)jt * 1152;
        unsigned bk0[4], bk1[4];
        ldsm4(bk0, kb);
        ldsm4(bk1, kb + 64);
        mma8(s, a[0], bk0);
        mma8(s, a[1], bk0 + 2);
        mma8(s, a[2], bk1);
        mma8(s, a[3], bk1 + 2);
        // exp2 (log2e folded into q scale and bias)
        float e0 = ex2(s[0]);
        float e1 = ex2(s[1]);
        float e2 = ex2(s[2]);
        float e3 = ex2(s[3]);
        rs0 += e0 + e1;
        rs1 += e2 + e3;
        // relayout C-frag -> A-frag, rna-rounded
        float t00 = __shfl_sync(0xffffffffu, e0, qsrc1);
        float t01 = __shfl_sync(0xffffffffu, e1, qsrc1);
        float t10 = __shfl_sync(0xffffffffu, e2, qsrc1);
        float t11 = __shfl_sync(0xffffffffu, e3, qsrc1);
        float u00 = __shfl_sync(0xffffffffu, e0, qsrc2);
        float u01 = __shfl_sync(0xffffffffu, e1, qsrc2);
        float u10 = __shfl_sync(0xffffffffu, e2, qsrc2);
        float u11 = __shfl_sync(0xffffffffu, e3, qsrc2);
        unsigned pa[4];
        pa[0] = rna(odd ? t01 : t00);
        pa[1] = rna(odd ? t11 : t10);
        pa[2] = rna(odd ? u01 : u00);
        pa[3] = rna(odd ? u11 : u10);
        // PV
        unsigned vb = vtb4 + (unsigned)jt * 32;
        unsigned bv0[4], bv1[4];
        ldsm4(bv0, vb);
        ldsm4(bv1, vb + 25344);
        mma8(oacc[0], pa, bv0);
        mma8(oacc[1], pa, bv0 + 2);
        mma8(oacc[2], pa, bv1);
        mma8(oacc[3], pa, bv1 + 2);
        bv = bv_next;
    }

    rs0 += __shfl_xor_sync(0xffffffffu, rs0, 1);
    rs0 += __shfl_xor_sync(0xffffffffu, rs0, 2);
    rs1 += __shfl_xor_sync(0xffffffffu, rs1, 1);
    rs1 += __shfl_xor_sync(0xffffffffu, rs1, 2);
    float si0 = 1.f / rs0, si1 = 1.f / rs1;

    size_t ob = ((size_t)win * 392 + qr) * 128 + head * 32;
    #pragma unroll
    for (int dt = 0; dt < 4; dt++) {
        int dc = dt * 8 + 2 * (lane & 3);
        float2 o0; o0.x = oacc[dt][0] * si0; o0.y = oacc[dt][1] * si0;
        *(float2*)(g_att + ob + dc) = o0;
        if (qr + 8 < 392) {
            float2 o1; o1.x = oacc[dt][2] * si1; o1.y = oacc[dt][3] * si1;
            *(float2*)(g_att + ob + 8 * 128 + dc) = o1;
        }
    }
}

// ---------------------------------------------------------------------------
// Kernel 2: single-pass flash attention. Block = (win, head), 384 thr, 1 sync.
// Smem ~107.5 KB -> 2 blocks/SM; 85-reg budget (no spills).
// ---------------------------------------------------------------------------
__global__ __launch_bounds__(384, 2) void attn_kernel()
{
    extern __shared__ float sm[];
    float* Ks = sm;                      // 392*36 = 14112
    float* Vt = Ks + 14112;              // 32*396 = 12672
    unsigned char* rid = (unsigned char*)(Vt + 12672);

    int bx = blockIdx.x;
    int win = bx >> 2, head = bx & 3;
    int tid = threadIdx.x;

    const float* qbase = g_qkv + (size_t)win * (392 * 384) + head * 32;
    const float* kbase = qbase + 128;
    const float* vbase = qbase + 256;

    int w2 = win & 127;
    int bt = ((w2 >> 6) == 1), bh = (((w2 >> 3) & 7) == 7), bw = ((w2 & 7) == 7);
    bool masked = bt || bh || bw;
    for (int l = tid; l < 392; l += 384) {
        int lt = l / 49; int r = l - lt * 49; int lh = r / 7; int lw = r - lh * 7;
        int rt = bt ? ((lt < 4) ? 1 : 2) : 0;
        int rh = bh ? ((lh < 4) ? 1 : 2) : 0;
        int rw = bw ? ((lw < 4) ? 1 : 2) : 0;
        rid[l] = (unsigned char)(rt * 9 + rh * 3 + rw);
    }
    // K rows rna-rounded
    for (int i = tid; i < 392 * 8; i += 384) {
        int j = i >> 3, c4 = i & 7;
        float4 v = *(const float4*)(kbase + (size_t)j * 384 + c4 * 4);
        float* d = Ks + j * 36 + c4 * 4;
        d[0] = u2f(rna(v.x)); d[1] = u2f(rna(v.y));
        d[2] = u2f(rna(v.z)); d[3] = u2f(rna(v.w));
    }
    // V transposed, rna-rounded
    for (int i = tid; i < 392 * 32; i += 384) {
        int j = i / 32, c = i & 31;
        Vt[c * 396 + j] = u2f(rna(vbase[(size_t)j * 384 + c]));
    }
    __syncthreads();   // the only block-wide sync

    int lane = tid & 31, warp = tid >> 5;
    unsigned ksb4 = sptr(Ks + (lane & 7) * 36 + ((lane >> 3) & 3) * 4);
    unsigned vtb4 = sptr(Vt + (((lane >> 4) & 1) * 8 + (lane & 7)) * 396
                            + ((lane >> 3) & 1) * 4);

    if (masked) {
        for (int mt = warp; mt < 25; mt += 12)
            attn_tile<true>(mt, lane, win, head, qbase, rid, ksb4, vtb4);
    } else {
        for (int mt = warp; mt < 25; mt += 12)
            attn_tile<false>(mt, lane, win, head, qbase, rid, ksb4, vtb4);
    }
}

// ---------------------------------------------------------------------------
// Kernel 3: proj GEMM, cp.async double-buffered, fused scatter.
// ---------------------------------------------------------------------------
__global__ __launch_bounds__(512, 2) void proj_kernel(
    const float* __restrict__ bias, float* __restrict__ out)
{
    extern __shared__ float sm[];
    float* Abuf = sm;
    float* Bbuf = sm + 2 * 4608;
    int* rowdst = (int*)(sm + 4 * 4608);

    int m0 = blockIdx.x * 128;
    int tid = threadIdx.x;
    if (tid < 128) rowdst[tid] = token_img_offset(m0 + tid);
    __syncthreads();

    int lane = tid & 31, warp = tid >> 5;
    int wm = warp >> 2, wn = warp & 3;

    float d[2][4][4];
    #pragma unroll
    for (int mi = 0; mi < 2; mi++)
        #pragma unroll
        for (int nj = 0; nj < 4; nj++)
            #pragma unroll
            for (int r = 0; r < 4; r++) d[mi][nj][r] = 0.f;

    int r0 = tid >> 3, f40 = (tid & 7) * 4;
    int r1 = (tid + 512) >> 3;

    {
        cpa16(sptr(Abuf + r0 * 36 + f40), g_att + (size_t)(m0 + r0) * 128 + f40);
        cpa16(sptr(Bbuf + r0 * 36 + f40), g_pwr + (size_t)r0 * 128 + f40);
        cpa16(sptr(Abuf + r1 * 36 + f40), g_att + (size_t)(m0 + r1) * 128 + f40);
        cpa16(sptr(Bbuf + r1 * 36 + f40), g_pwr + (size_t)r1 * 128 + f40);
        asm volatile("cp.async.commit_group;");
    }
    #pragma unroll
    for (int kc = 0; kc < 4; kc++) {
        if (kc < 3) {
            int bi = (kc + 1) & 1, kof = (kc + 1) * 32;
            cpa16(sptr(Abuf + bi * 4608 + r0 * 36 + f40), g_att + (size_t)(m0 + r0) * 128 + kof + f40);
            cpa16(sptr(Bbuf + bi * 4608 + r0 * 36 + f40), g_pwr + (size_t)r0 * 128 + kof + f40);
            cpa16(sptr(Abuf + bi * 4608 + r1 * 36 + f40), g_att + (size_t)(m0 + r1) * 128 + kof + f40);
            cpa16(sptr(Bbuf + bi * 4608 + r1 * 36 + f40), g_pwr + (size_t)r1 * 128 + kof + f40);
            asm volatile("cp.async.commit_group;");
            asm volatile("cp.async.wait_group 1;");
        } else {
            asm volatile("cp.async.wait_group 0;");
        }
        __syncthreads();
        gemm1_core(Abuf + (kc & 1) * 4608, Bbuf + (kc & 1) * 4608, lane, wm, wn, d);
        __syncthreads();
    }

    #pragma unroll
    for (int mi = 0; mi < 2; mi++) {
        int ml = wm * 32 + mi * 16 + (lane >> 2);
        #pragma unroll
        for (int nj = 0; nj < 4; nj++) {
            int col = wn * 32 + nj * 8 + (lane & 3) * 2;
            float2 bvv = *(const float2*)(bias + col);
            float2 o0, o1;
            o0.x = d[mi][nj][0] + bvv.x; o0.y = d[mi][nj][1] + bvv.y;
            o1.x = d[mi][nj][2] + bvv.x; o1.y = d[mi][nj][3] + bvv.y;
            *(float2*)(out + rowdst[ml] + col) = o0;
            *(float2*)(out + rowdst[ml + 8] + col) = o1;
        }
    }
}

// ---------------------------------------------------------------------------
extern "C" void kernel_launch(void* const* d_in, const int* in_sizes, int n_in,
                              void* d_out, int out_size)
{
    const float* x   = (const float*)d_in[0];
    const float* qw  = (const float*)d_in[1];
    const float* qb  = (const float*)d_in[2];
    const float* pw  = (const float*)d_in[3];
    const float* pb  = (const float*)d_in[4];
    const float* rpb = (const float*)d_in[5];
    float* out = (float*)d_out;

    const int smemG = 4 * 4608 * 4 + 512;            // 74,240 B
    const int smemA = (14112 + 12672) * 4 + 392 + 8; // 107,536 B

    cudaFuncSetAttribute(qkv_kernel,  cudaFuncAttributeMaxDynamicSharedMemorySize, smemG);
    cudaFuncSetAttribute(attn_kernel, cudaFuncAttributeMaxDynamicSharedMemorySize, smemA);
    cudaFuncSetAttribute(proj_kernel, cudaFuncAttributeMaxDynamicSharedMemorySize, smemG);

    prep_kernel<<<869, 256>>>(rpb, qw, pw);
    qkv_kernel<<<dim3(3, 784), 512, smemG>>>(x, qb);
    attn_kernel<<<1024, 384, smemA>>>();
    proj_kernel<<<784, 512, smemG>>>(pb, out);
}

// round 11
// speedup vs baseline: 3.3713x; 1.2664x over previous
#include <cuda_runtime.h>
#include <cuda_fp16.h>

#define TOKENS 100352   // 256 windows * 392 tokens

__device__ float  g_qkv[(size_t)TOKENS * 384];   // [token][384]: q*scale*log2e | k | v
__device__ float  g_att[(size_t)TOKENS * 128];   // attention out, token-major
__device__ float4 g_rpbT[4 * 25 * 50 * 32];      // frag-ordered rel-pos bias * log2e (+pad jt)
__device__ float  g_qwr[384 * 128];              // rna-rounded qkv weight
__device__ float  g_pwr[128 * 128];              // rna-rounded proj weight

__device__ __forceinline__ unsigned rna(float f) {
    unsigned u; asm("cvt.rna.tf32.f32 %0, %1;" : "=r"(u) : "f"(f)); return u;
}
__device__ __forceinline__ float u2f(unsigned u) { return __uint_as_float(u); }
__device__ __forceinline__ float ex2(float x) {
    float r; asm("ex2.approx.ftz.f32 %0, %1;" : "=f"(r) : "f"(x)); return r;
}
__device__ __forceinline__ unsigned h2u(float a, float b) {
    __half2 h = __floats2half2_rn(a, b);
    return *(unsigned*)&h;
}
__device__ __forceinline__ void mma8(float* d, const unsigned* a, const unsigned* b) {
    asm volatile("mma.sync.aligned.m16n8k8.row.col.f32.tf32.tf32.f32 "
        "{%0,%1,%2,%3}, {%4,%5,%6,%7}, {%8,%9}, {%0,%1,%2,%3};"
        : "+f"(d[0]), "+f"(d[1]), "+f"(d[2]), "+f"(d[3])
        : "r"(a[0]), "r"(a[1]), "r"(a[2]), "r"(a[3]), "r"(b[0]), "r"(b[1]));
}
__device__ __forceinline__ void mmah(float* d, const unsigned* a, const unsigned* b) {
    asm volatile("mma.sync.aligned.m16n8k16.row.col.f32.f16.f16.f32 "
        "{%0,%1,%2,%3}, {%4,%5,%6,%7}, {%8,%9}, {%0,%1,%2,%3};"
        : "+f"(d[0]), "+f"(d[1]), "+f"(d[2]), "+f"(d[3])
        : "r"(a[0]), "r"(a[1]), "r"(a[2]), "r"(a[3]), "r"(b[0]), "r"(b[1]));
}
__device__ __forceinline__ void ldsm4(unsigned* r, unsigned a) {
    asm volatile("ldmatrix.sync.aligned.m8n8.x4.shared.b16 {%0,%1,%2,%3},[%4];"
        : "=r"(r[0]), "=r"(r[1]), "=r"(r[2]), "=r"(r[3]) : "r"(a));
}
__device__ __forceinline__ unsigned sptr(const void* p) {
    return (unsigned)__cvta_generic_to_shared(p);
}
__device__ __forceinline__ void cpa16(unsigned dst, const float* src) {
    asm volatile("cp.async.cg.shared.global [%0],[%1],16;" :: "r"(dst), "l"(src));
}

// token -> element offset in [B,T,H,W,C] with cyclic shift (+4,+3,+3)
__device__ __forceinline__ int token_img_offset(int m) {
    int win = m / 392;
    int l   = m - win * 392;
    int b   = win >> 7;
    int w2  = win & 127;
    int it  = w2 >> 6, ih = (w2 >> 3) & 7, iw = w2 & 7;
    int lt  = l / 49; int r = l - lt * 49;
    int lh  = r / 7;  int lw = r - lh * 7;
    int t = (it * 8 + lt + 4) & 15;
    int h = ih * 7 + lh + 3; if (h >= 56) h -= 56;
    int w = iw * 7 + lw + 3; if (w >= 56) w -= 56;
    return (((b * 16 + t) * 56 + h) * 56 + w) * 128;
}

// ---------------------------------------------------------------------------
// Kernel 0: pre-pack bias (frag order, *log2e, 50 jt with -1e4 pad) + weights.
// ---------------------------------------------------------------------------
__global__ __launch_bounds__(256) void prep_kernel(
    const float* __restrict__ rpb, const float* __restrict__ qw,
    const float* __restrict__ pw)
{
    int i = blockIdx.x * 256 + threadIdx.x;
    const int NB = 4 * 25 * 50 * 32;          // 160000
    if (i < NB) {
        int lane = i & 31; int t = i >> 5;
        int jt = t % 50; t /= 50;
        int mt = t % 25; int h = t / 25;
        if (jt == 49) {
            g_rpbT[i] = make_float4(-1e4f, -1e4f, -1e4f, -1e4f);
        } else {
            int qr = mt * 16 + (lane >> 2);
            int qc0 = (qr < 392) ? qr : 391;
            int qc1 = (qr + 8 < 392) ? qr + 8 : 391;
            int jc = jt * 8 + 2 * (lane & 3);
            const float* bp = rpb + (size_t)h * (392 * 392);
            const float L2E = 1.4426950408889634f;
            float4 v;
            v.x = bp[(size_t)qc0 * 392 + jc] * L2E;
            v.y = bp[(size_t)qc0 * 392 + jc + 1] * L2E;
            v.z = bp[(size_t)qc1 * 392 + jc] * L2E;
            v.w = bp[(size_t)qc1 * 392 + jc + 1] * L2E;
            g_rpbT[i] = v;
        }
    } else if (i < NB + 384 * 128) {
        int k = i - NB;
        g_qwr[k] = u2f(rna(qw[k]));
    } else if (i < NB + 384 * 128 + 128 * 128) {
        int k = i - NB - 384 * 128;
        g_pwr[k] = u2f(rna(pw[k]));
    }
}

// ---------------------------------------------------------------------------
// 1xTF32 GEMM core: 128x128 tile, 512 thr, LDSM operands.
// ---------------------------------------------------------------------------
__device__ __forceinline__ void gemm1_core(
    float* As, float* Bs, int lane, int wm, int wn, float d[2][4][4])
{
    unsigned aoff = sptr(As + (wm * 32 + ((lane >> 3) & 1) * 8 + (lane & 7)) * 36
                            + ((lane >> 4) & 1) * 4);
    unsigned boff = sptr(Bs + (wn * 32 + ((lane >> 4) & 1) * 8 + (lane & 7)) * 36
                            + ((lane >> 3) & 1) * 4);
    const unsigned R16 = 16 * 36 * 4;

    #pragma unroll
    for (int ks = 0; ks < 4; ks++) {
        unsigned ka = ks * 32;
        unsigned a[2][4], b[2][4];
        ldsm4(a[0], aoff + ka);  ldsm4(a[1], aoff + ka + R16);
        ldsm4(b[0], boff + ka);  ldsm4(b[1], boff + ka + R16);
        #pragma unroll
        for (int mi = 0; mi < 2; mi++)
            #pragma unroll
            for (int p = 0; p < 2; p++) {
                mma8(d[mi][2 * p],     a[mi], b[p]);
                mma8(d[mi][2 * p + 1], a[mi], b[p] + 2);
            }
    }
}

// ---------------------------------------------------------------------------
// Kernel 1: QKV GEMM, cp.async double-buffered, fused gather. grid (3, 784).
// ---------------------------------------------------------------------------
__global__ __launch_bounds__(512, 2) void qkv_kernel(
    const float* __restrict__ x, const float* __restrict__ bias)
{
    extern __shared__ float sm[];
    float* Abuf = sm;                 // [2][128*36]
    float* Bbuf = sm + 2 * 4608;      // [2][128*36]
    int* rowsrc = (int*)(sm + 4 * 4608);

    int m0 = blockIdx.y * 128, n0 = blockIdx.x * 128;
    int tid = threadIdx.x;
    if (tid < 128) rowsrc[tid] = token_img_offset(m0 + tid);
    __syncthreads();

    int lane = tid & 31, warp = tid >> 5;
    int wm = warp >> 2, wn = warp & 3;

    float d[2][4][4];
    #pragma unroll
    for (int mi = 0; mi < 2; mi++)
        #pragma unroll
        for (int nj = 0; nj < 4; nj++)
            #pragma unroll
            for (int r = 0; r < 4; r++) d[mi][nj][r] = 0.f;

    int r0 = tid >> 3, f40 = (tid & 7) * 4;
    int r1 = (tid + 512) >> 3;

    {
        cpa16(sptr(Abuf + r0 * 36 + f40), x + rowsrc[r0] + f40);
        cpa16(sptr(Bbuf + r0 * 36 + f40), g_qwr + (size_t)(n0 + r0) * 128 + f40);
        cpa16(sptr(Abuf + r1 * 36 + f40), x + rowsrc[r1] + f40);
        cpa16(sptr(Bbuf + r1 * 36 + f40), g_qwr + (size_t)(n0 + r1) * 128 + f40);
        asm volatile("cp.async.commit_group;");
    }
    #pragma unroll
    for (int kc = 0; kc < 4; kc++) {
        if (kc < 3) {
            int bi = (kc + 1) & 1, kof = (kc + 1) * 32;
            cpa16(sptr(Abuf + bi * 4608 + r0 * 36 + f40), x + rowsrc[r0] + kof + f40);
            cpa16(sptr(Bbuf + bi * 4608 + r0 * 36 + f40), g_qwr + (size_t)(n0 + r0) * 128 + kof + f40);
            cpa16(sptr(Abuf + bi * 4608 + r1 * 36 + f40), x + rowsrc[r1] + kof + f40);
            cpa16(sptr(Bbuf + bi * 4608 + r1 * 36 + f40), g_qwr + (size_t)(n0 + r1) * 128 + kof + f40);
            asm volatile("cp.async.commit_group;");
            asm volatile("cp.async.wait_group 1;");
        } else {
            asm volatile("cp.async.wait_group 0;");
        }
        __syncthreads();
        gemm1_core(Abuf + (kc & 1) * 4608, Bbuf + (kc & 1) * 4608, lane, wm, wn, d);
        __syncthreads();
    }

    #pragma unroll
    for (int mi = 0; mi < 2; mi++) {
        int row = m0 + wm * 32 + mi * 16 + (lane >> 2);
        #pragma unroll
        for (int nj = 0; nj < 4; nj++) {
            int col = n0 + wn * 32 + nj * 8 + (lane & 3) * 2;
            float sc = (col < 128) ? 0.25503486f : 1.0f;   // hd^-0.5 * log2e
            float2 bv = *(const float2*)(bias + col);
            float2 o0, o1;
            o0.x = (d[mi][nj][0] + bv.x) * sc; o0.y = (d[mi][nj][1] + bv.y) * sc;
            o1.x = (d[mi][nj][2] + bv.x) * sc; o1.y = (d[mi][nj][3] + bv.y) * sc;
            *(float2*)(g_qkv + (size_t)row * 384 + col) = o0;
            *(float2*)(g_qkv + (size_t)(row + 8) * 384 + col) = o1;
        }
    }
}

// ---------------------------------------------------------------------------
// Attention per-warp core (fp16 m16n8k16), templated on mask presence.
// ---------------------------------------------------------------------------
template<bool MASKED>
__device__ __forceinline__ void attn_tile(
    int mt, int lane, int win, int head,
    const float* qbase, const unsigned char* rid,
    unsigned ksb, unsigned vtb)
{
    int qr = mt * 16 + (lane >> 2);
    int qc0 = (qr < 392) ? qr : 391;
    int qc1 = (qr + 8 < 392) ? (qr + 8) : 391;

    // Q A-fragments (2 x k16), fp16, loaded from gmem
    unsigned aq[2][4];
    {
        const float2* q0p = (const float2*)(qbase + (size_t)qc0 * 384) + (lane & 3);
        const float2* q1p = (const float2*)(qbase + (size_t)qc1 * 384) + (lane & 3);
        #pragma unroll
        for (int kk = 0; kk < 2; kk++) {
            float2 f;
            f = __ldg(q0p + kk * 8);     aq[kk][0] = h2u(f.x, f.y);
            f = __ldg(q1p + kk * 8);     aq[kk][1] = h2u(f.x, f.y);
            f = __ldg(q0p + kk * 8 + 4); aq[kk][2] = h2u(f.x, f.y);
            f = __ldg(q1p + kk * 8 + 4); aq[kk][3] = h2u(f.x, f.y);
        }
    }

    unsigned char rq0 = 0, rq1 = 0;
    if (MASKED) { rq0 = rid[qc0]; rq1 = rid[qc1]; }
    const float4* bb = g_rpbT + ((head * 25 + mt) * 50) * 32 + lane;

    float oacc[4][4];
    #pragma unroll
    for (int dt = 0; dt < 4; dt++)
        #pragma unroll
        for (int r = 0; r < 4; r++) oacc[dt][r] = 0.f;
    float rs0 = 0.f, rs1 = 0.f;

    float4 bvA = __ldg(bb);
    float4 bvB = __ldg(bb + 32);

    #pragma unroll 2
    for (int p = 0; p < 25; p++) {
        float4 nA, nB;
        if (p < 24) {
            nA = __ldg(bb + (2 * p + 2) * 32);
            nB = __ldg(bb + (2 * p + 3) * 32);
        }
        // S accumulators init with (masked) bias
        float sA[4], sB[4];
        if (MASKED) {
            int jc = p * 16 + 2 * (lane & 3);
            unsigned char ra0 = rid[jc], ra1 = rid[jc + 1];
            unsigned char rb0 = rid[jc + 8], rb1 = rid[jc + 9];
            sA[0] = (rq0 == ra0) ? bvA.x : -1e4f;
            sA[1] = (rq0 == ra1) ? bvA.y : -1e4f;
            sA[2] = (rq1 == ra0) ? bvA.z : -1e4f;
            sA[3] = (rq1 == ra1) ? bvA.w : -1e4f;
            sB[0] = (rq0 == rb0) ? bvB.x : -1e4f;
            sB[1] = (rq0 == rb1) ? bvB.y : -1e4f;
            sB[2] = (rq1 == rb0) ? bvB.z : -1e4f;
            sB[3] = (rq1 == rb1) ? bvB.w : -1e4f;
        } else {
            sA[0] = bvA.x; sA[1] = bvA.y; sA[2] = bvA.z; sA[3] = bvA.w;
            sB[0] = bvB.x; sB[1] = bvB.y; sB[2] = bvB.z; sB[3] = bvB.w;
        }
        // S = Q K^T for the two 8-j tiles of this 16-j window
        unsigned kbA = ksb + (unsigned)p * 1280;     // 16 rows * 80 B
        unsigned b0[4], b1[4];
        ldsm4(b0, kbA);
        ldsm4(b1, kbA + 640);                        // +8 rows
        mmah(sA, aq[0], b0); mmah(sA, aq[1], b0 + 2);
        mmah(sB, aq[0], b1); mmah(sB, aq[1], b1 + 2);
        // exp2
        float e0A = ex2(sA[0]), e1A = ex2(sA[1]), e2A = ex2(sA[2]), e3A = ex2(sA[3]);
        float e0B = ex2(sB[0]), e1B = ex2(sB[1]), e2B = ex2(sB[2]), e3B = ex2(sB[3]);
        rs0 += (e0A + e1A) + (e0B + e1B);
        rs1 += (e2A + e3A) + (e2B + e3B);
        // C-frag -> fp16 A-frag: pure local pack, no shuffles
        unsigned pa[4];
        pa[0] = h2u(e0A, e1A);
        pa[1] = h2u(e2A, e3A);
        pa[2] = h2u(e0B, e1B);
        pa[3] = h2u(e2B, e3B);
        // PV: P(16x16) x V(16x32)
        unsigned vb = vtb + (unsigned)p * 32;        // 16 j-halves
        unsigned v0[4], v1[4];
        ldsm4(v0, vb);
        ldsm4(v1, vb + 16 * 816);                    // d 16..31
        mmah(oacc[0], pa, v0); mmah(oacc[1], pa, v0 + 2);
        mmah(oacc[2], pa, v1); mmah(oacc[3], pa, v1 + 2);
        bvA = nA; bvB = nB;
    }

    rs0 += __shfl_xor_sync(0xffffffffu, rs0, 1);
    rs0 += __shfl_xor_sync(0xffffffffu, rs0, 2);
    rs1 += __shfl_xor_sync(0xffffffffu, rs1, 1);
    rs1 += __shfl_xor_sync(0xffffffffu, rs1, 2);
    float si0 = 1.f / rs0, si1 = 1.f / rs1;

    size_t ob = ((size_t)win * 392 + qr) * 128 + head * 32;
    #pragma unroll
    for (int dt = 0; dt < 4; dt++) {
        int dc = dt * 8 + 2 * (lane & 3);
        float2 o0; o0.x = oacc[dt][0] * si0; o0.y = oacc[dt][1] * si0;
        *(float2*)(g_att + ob + dc) = o0;
        if (qr + 8 < 392) {
            float2 o1; o1.x = oacc[dt][2] * si1; o1.y = oacc[dt][3] * si1;
            *(float2*)(g_att + ob + 8 * 128 + dc) = o1;
        }
    }
}

// ---------------------------------------------------------------------------
// Kernel 2: single-pass flash attention (fp16 mma). 416 thr (13 warps), 1 sync.
// Smem: Ksh[400][40]h | Vth[32][408]h | rid[400]  = 58,512 B -> 2 blocks/SM
// ---------------------------------------------------------------------------
__global__ __launch_bounds__(416, 2) void attn_kernel()
{
    extern __shared__ __align__(16) char smc[];
    __half* Ksh = (__half*)smc;                      // 32,000 B
    __half* Vth = (__half*)(smc + 32000);            // 26,112 B
    unsigned char* rid = (unsigned char*)(smc + 32000 + 26112);  // 400

    int bx = blockIdx.x;
    int win = bx >> 2, head = bx & 3;
    int tid = threadIdx.x;

    const float* qbase = g_qkv + (size_t)win * (392 * 384) + head * 32;
    const float* kbase = qbase + 128;
    const float* vbase = qbase + 256;

    int w2 = win & 127;
    int bt = ((w2 >> 6) == 1), bh = (((w2 >> 3) & 7) == 7), bw = ((w2 & 7) == 7);
    bool masked = bt || bh || bw;
    for (int l = tid; l < 400; l += 416) {
        unsigned char v = 255;
        if (l < 392) {
            int lt = l / 49; int r = l - lt * 49; int lh = r / 7; int lw = r - lh * 7;
            int rt = bt ? ((lt < 4) ? 1 : 2) : 0;
            int rh = bh ? ((lh < 4) ? 1 : 2) : 0;
            int rw = bw ? ((lw < 4) ? 1 : 2) : 0;
            v = (unsigned char)(rt * 9 + rh * 3 + rw);
        }
        rid[l] = v;
    }
    // K: fp32 -> fp16 rows (pad rows 392..399 = 0)
    for (int i = tid; i < 400 * 16; i += 416) {
        int j = i >> 4, c2 = i & 15;
        __half2 hv;
        if (j < 392) {
            float2 f = *(const float2*)(kbase + (size_t)j * 384 + c2 * 2);
            hv = __floats2half2_rn(f.x, f.y);
        } else {
            hv = __floats2half2_rn(0.f, 0.f);
        }
        *((__half2*)(Ksh + j * 40) + c2) = hv;
    }
    // V transposed fp16 (pad j 392..407 = 0)
    for (int i = tid; i < 32 * 408; i += 416) {
        int d = i / 408, j = i - d * 408;
        float f = (j < 392) ? vbase[(size_t)j * 384 + d] : 0.f;
        Vth[d * 408 + j] = __float2half_rn(f);
    }
    __syncthreads();   // the only block-wide sync

    int lane = tid & 31, warp = tid >> 5;
    unsigned ksb = sptr(Ksh) + (lane & 7) * 80 + (lane >> 3) * 16;
    unsigned vtb = sptr(Vth) + (((lane >> 4) & 1) * 8 + (lane & 7)) * 816
                             + ((lane >> 3) & 1) * 16;

    if (masked) {
        for (int mt = warp; mt < 25; mt += 13)
            attn_tile<true>(mt, lane, win, head, qbase, rid, ksb, vtb);
    } else {
        for (int mt = warp; mt < 25; mt += 13)
            attn_tile<false>(mt, lane, win, head, qbase, rid, ksb, vtb);
    }
}

// ---------------------------------------------------------------------------
// Kernel 3: proj GEMM, cp.async double-buffered, fused scatter.
// ---------------------------------------------------------------------------
__global__ __launch_bounds__(512, 2) void proj_kernel(
    const float* __restrict__ bias, float* __restrict__ out)
{
    extern __shared__ float sm[];
    float* Abuf = sm;
    float* Bbuf = sm + 2 * 4608;
    int* rowdst = (int*)(sm + 4 * 4608);

    int m0 = blockIdx.x * 128;
    int tid = threadIdx.x;
    if (tid < 128) rowdst[tid] = token_img_offset(m0 + tid);
    __syncthreads();

    int lane = tid & 31, warp = tid >> 5;
    int wm = warp >> 2, wn = warp & 3;

    float d[2][4][4];
    #pragma unroll
    for (int mi = 0; mi < 2; mi++)
        #pragma unroll
        for (int nj = 0; nj < 4; nj++)
            #pragma unroll
            for (int r = 0; r < 4; r++) d[mi][nj][r] = 0.f;

    int r0 = tid >> 3, f40 = (tid & 7) * 4;
    int r1 = (tid + 512) >> 3;

    {
        cpa16(sptr(Abuf + r0 * 36 + f40), g_att + (size_t)(m0 + r0) * 128 + f40);
        cpa16(sptr(Bbuf + r0 * 36 + f40), g_pwr + (size_t)r0 * 128 + f40);
        cpa16(sptr(Abuf + r1 * 36 + f40), g_att + (size_t)(m0 + r1) * 128 + f40);
        cpa16(sptr(Bbuf + r1 * 36 + f40), g_pwr + (size_t)r1 * 128 + f40);
        asm volatile("cp.async.commit_group;");
    }
    #pragma unroll
    for (int kc = 0; kc < 4; kc++) {
        if (kc < 3) {
            int bi = (kc + 1) & 1, kof = (kc + 1) * 32;
            cpa16(sptr(Abuf + bi * 4608 + r0 * 36 + f40), g_att + (size_t)(m0 + r0) * 128 + kof + f40);
            cpa16(sptr(Bbuf + bi * 4608 + r0 * 36 + f40), g_pwr + (size_t)r0 * 128 + kof + f40);
            cpa16(sptr(Abuf + bi * 4608 + r1 * 36 + f40), g_att + (size_t)(m0 + r1) * 128 + kof + f40);
            cpa16(sptr(Bbuf + bi * 4608 + r1 * 36 + f40), g_pwr + (size_t)r1 * 128 + kof + f40);
            asm volatile("cp.async.commit_group;");
            asm volatile("cp.async.wait_group 1;");
        } else {
            asm volatile("cp.async.wait_group 0;");
        }
        __syncthreads();
        gemm1_core(Abuf + (kc & 1) * 4608, Bbuf + (kc & 1) * 4608, lane, wm, wn, d);
        __syncthreads();
    }

    #pragma unroll
    for (int mi = 0; mi < 2; mi++) {
        int ml = wm * 32 + mi * 16 + (lane >> 2);
        #pragma unroll
        for (int nj = 0; nj < 4; nj++) {
            int col = wn * 32 + nj * 8 + (lane & 3) * 2;
            float2 bvv = *(const float2*)(bias + col);
            float2 o0, o1;
            o0.x = d[mi][nj][0] + bvv.x; o0.y = d[mi][nj][1] + bvv.y;
            o1.x = d[mi][nj][2] + bvv.x; o1.y = d[mi][nj][3] + bvv.y;
            *(float2*)(out + rowdst[ml] + col) = o0;
            *(float2*)(out + rowdst[ml + 8] + col) = o1;
        }
    }
}

// ---------------------------------------------------------------------------
extern "C" void kernel_launch(void* const* d_in, const int* in_sizes, int n_in,
                              void* d_out, int out_size)
{
    const float* x   = (const float*)d_in[0];
    const float* qw  = (const float*)d_in[1];
    const float* qb  = (const float*)d_in[2];
    const float* pw  = (const float*)d_in[3];
    const float* pb  = (const float*)d_in[4];
    const float* rpb = (const float*)d_in[5];
    float* out = (float*)d_out;

    const int smemG = 4 * 4608 * 4 + 512;    // 74,240 B
    const int smemA = 32000 + 26112 + 400;   // 58,512 B

    cudaFuncSetAttribute(qkv_kernel,  cudaFuncAttributeMaxDynamicSharedMemorySize, smemG);
    cudaFuncSetAttribute(attn_kernel, cudaFuncAttributeMaxDynamicSharedMemorySize, smemA);
    cudaFuncSetAttribute(proj_kernel, cudaFuncAttributeMaxDynamicSharedMemorySize, smemG);

    prep_kernel<<<881, 256>>>(rpb, qw, pw);
    qkv_kernel<<<dim3(3, 784), 512, smemG>>>(x, qb);
    attn_kernel<<<1024, 416, smemA>>>();
    proj_kernel<<<784, 512, smemG>>>(pb, out);
}

// round 14
// speedup vs baseline: 4.1430x; 1.2289x over previous
#include <cuda_runtime.h>
#include <cuda_fp16.h>

#define TOKENS 100352   // 256 windows * 392 tokens

__device__ __half  g_qkvh[(size_t)TOKENS * 384]; // [token][384] fp16: q*scale*log2e | k | v
__device__ __half  g_atth[(size_t)TOKENS * 128]; // attention out fp16, token-major
__device__ float4  g_rpbT[4 * 25 * 50 * 32];     // frag-ordered rel-pos bias * log2e (+pad jt)
__device__ float   g_qwr[384 * 128];             // rna-rounded qkv weight (fp32/tf32)
__device__ __half  g_pwrh[128 * 128];            // fp16 proj weight

__device__ __forceinline__ unsigned rna(float f) {
    unsigned u; asm("cvt.rna.tf32.f32 %0, %1;" : "=r"(u) : "f"(f)); return u;
}
__device__ __forceinline__ float u2f(unsigned u) { return __uint_as_float(u); }
__device__ __forceinline__ float ex2(float x) {
    float r; asm("ex2.approx.ftz.f32 %0, %1;" : "=f"(r) : "f"(x)); return r;
}
__device__ __forceinline__ unsigned h2u(float a, float b) {
    __half2 h = __floats2half2_rn(a, b);
    return *(unsigned*)&h;
}
__device__ __forceinline__ void mma8(float* d, const unsigned* a, const unsigned* b) {
    asm volatile("mma.sync.aligned.m16n8k8.row.col.f32.tf32.tf32.f32 "
        "{%0,%1,%2,%3}, {%4,%5,%6,%7}, {%8,%9}, {%0,%1,%2,%3};"
        : "+f"(d[0]), "+f"(d[1]), "+f"(d[2]), "+f"(d[3])
        : "r"(a[0]), "r"(a[1]), "r"(a[2]), "r"(a[3]), "r"(b[0]), "r"(b[1]));
}
__device__ __forceinline__ void mmah(float* d, const unsigned* a, const unsigned* b) {
    asm volatile("mma.sync.aligned.m16n8k16.row.col.f32.f16.f16.f32 "
        "{%0,%1,%2,%3}, {%4,%5,%6,%7}, {%8,%9}, {%0,%1,%2,%3};"
        : "+f"(d[0]), "+f"(d[1]), "+f"(d[2]), "+f"(d[3])
        : "r"(a[0]), "r"(a[1]), "r"(a[2]), "r"(a[3]), "r"(b[0]), "r"(b[1]));
}
__device__ __forceinline__ void ldsm4(unsigned* r, unsigned a) {
    asm volatile("ldmatrix.sync.aligned.m8n8.x4.shared.b16 {%0,%1,%2,%3},[%4];"
        : "=r"(r[0]), "=r"(r[1]), "=r"(r[2]), "=r"(r[3]) : "r"(a));
}
__device__ __forceinline__ unsigned sptr(const void* p) {
    return (unsigned)__cvta_generic_to_shared(p);
}
__device__ __forceinline__ void cpa16(unsigned dst, const void* src) {
    asm volatile("cp.async.cg.shared.global [%0],[%1],16;" :: "r"(dst), "l"(src));
}

// token -> element offset in [B,T,H,W,C] with cyclic shift (+4,+3,+3)
__device__ __forceinline__ int token_img_offset(int m) {
    int win = m / 392;
    int l   = m - win * 392;
    int b   = win >> 7;
    int w2  = win & 127;
    int it  = w2 >> 6, ih = (w2 >> 3) & 7, iw = w2 & 7;
    int lt  = l / 49; int r = l - lt * 49;
    int lh  = r / 7;  int lw = r - lh * 7;
    int t = (it * 8 + lt + 4) & 15;
    int h = ih * 7 + lh + 3; if (h >= 56) h -= 56;
    int w = iw * 7 + lw + 3; if (w >= 56) w -= 56;
    return (((b * 16 + t) * 56 + h) * 56 + w) * 128;
}

// ---------------------------------------------------------------------------
// Kernel 0: pre-pack bias (frag order, *log2e, 50 jt with -1e4 pad) + weights.
// 225536 = 160000 (bias) + 49152 (qw fp32) + 16384 (pw fp16) = 881*256.
// ---------------------------------------------------------------------------
__global__ __launch_bounds__(256) void prep_kernel(
    const float* __restrict__ rpb, const float* __restrict__ qw,
    const float* __restrict__ pw)
{
    int i = blockIdx.x * 256 + threadIdx.x;
    const int NB = 4 * 25 * 50 * 32;          // 160000
    if (i < NB) {
        int lane = i & 31; int t = i >> 5;
        int jt = t % 50; t /= 50;
        int mt = t % 25; int h = t / 25;
        if (jt == 49) {
            g_rpbT[i] = make_float4(-1e4f, -1e4f, -1e4f, -1e4f);
        } else {
            int qr = mt * 16 + (lane >> 2);
            int qc0 = (qr < 392) ? qr : 391;
            int qc1 = (qr + 8 < 392) ? qr + 8 : 391;
            int jc = jt * 8 + 2 * (lane & 3);
            const float* bp = rpb + (size_t)h * (392 * 392);
            const float L2E = 1.4426950408889634f;
            float4 v;
            v.x = bp[(size_t)qc0 * 392 + jc] * L2E;
            v.y = bp[(size_t)qc0 * 392 + jc + 1] * L2E;
            v.z = bp[(size_t)qc1 * 392 + jc] * L2E;
            v.w = bp[(size_t)qc1 * 392 + jc + 1] * L2E;
            g_rpbT[i] = v;
        }
    } else if (i < NB + 384 * 128) {
        int k = i - NB;
        g_qwr[k] = u2f(rna(qw[k]));
    } else if (i < NB + 384 * 128 + 128 * 128) {
        int k = i - NB - 384 * 128;
        g_pwrh[k] = __float2half_rn(pw[k]);
    }
}

// ---------------------------------------------------------------------------
// 1xTF32 GEMM core: 128x128 tile, 512 thr, LDSM operands.
// ---------------------------------------------------------------------------
__device__ __forceinline__ void gemm1_core(
    float* As, float* Bs, int lane, int wm, int wn, float d[2][4][4])
{
    unsigned aoff = sptr(As + (wm * 32 + ((lane >> 3) & 1) * 8 + (lane & 7)) * 36
                            + ((lane >> 4) & 1) * 4);
    unsigned boff = sptr(Bs + (wn * 32 + ((lane >> 4) & 1) * 8 + (lane & 7)) * 36
                            + ((lane >> 3) & 1) * 4);
    const unsigned R16 = 16 * 36 * 4;

    #pragma unroll
    for (int ks = 0; ks < 4; ks++) {
        unsigned ka = ks * 32;
        unsigned a[2][4], b[2][4];
        ldsm4(a[0], aoff + ka);  ldsm4(a[1], aoff + ka + R16);
        ldsm4(b[0], boff + ka);  ldsm4(b[1], boff + ka + R16);
        #pragma unroll
        for (int mi = 0; mi < 2; mi++)
            #pragma unroll
            for (int p = 0; p < 2; p++) {
                mma8(d[mi][2 * p],     a[mi], b[p]);
                mma8(d[mi][2 * p + 1], a[mi], b[p] + 2);
            }
    }
}

// ---------------------------------------------------------------------------
// Kernel 1: QKV GEMM (tf32), cp.async double-buffered, fused gather,
// fp16 output. grid (3, 784).
// ---------------------------------------------------------------------------
__global__ __launch_bounds__(512, 2) void qkv_kernel(
    const float* __restrict__ x, const float* __restrict__ bias)
{
    extern __shared__ float sm[];
    float* Abuf = sm;                 // [2][128*36]
    float* Bbuf = sm + 2 * 4608;      // [2][128*36]
    int* rowsrc = (int*)(sm + 4 * 4608);

    int m0 = blockIdx.y * 128, n0 = blockIdx.x * 128;
    int tid = threadIdx.x;
    if (tid < 128) rowsrc[tid] = token_img_offset(m0 + tid);
    __syncthreads();

    int lane = tid & 31, warp = tid >> 5;
    int wm = warp >> 2, wn = warp & 3;

    float d[2][4][4];
    #pragma unroll
    for (int mi = 0; mi < 2; mi++)
        #pragma unroll
        for (int nj = 0; nj < 4; nj++)
            #pragma unroll
            for (int r = 0; r < 4; r++) d[mi][nj][r] = 0.f;

    int r0 = tid >> 3, f40 = (tid & 7) * 4;
    int r1 = (tid + 512) >> 3;

    {
        cpa16(sptr(Abuf + r0 * 36 + f40), x + rowsrc[r0] + f40);
        cpa16(sptr(Bbuf + r0 * 36 + f40), g_qwr + (size_t)(n0 + r0) * 128 + f40);
        cpa16(sptr(Abuf + r1 * 36 + f40), x + rowsrc[r1] + f40);
        cpa16(sptr(Bbuf + r1 * 36 + f40), g_qwr + (size_t)(n0 + r1) * 128 + f40);
        asm volatile("cp.async.commit_group;");
    }
    #pragma unroll
    for (int kc = 0; kc < 4; kc++) {
        if (kc < 3) {
            int bi = (kc + 1) & 1, kof = (kc + 1) * 32;
            cpa16(sptr(Abuf + bi * 4608 + r0 * 36 + f40), x + rowsrc[r0] + kof + f40);
            cpa16(sptr(Bbuf + bi * 4608 + r0 * 36 + f40), g_qwr + (size_t)(n0 + r0) * 128 + kof + f40);
            cpa16(sptr(Abuf + bi * 4608 + r1 * 36 + f40), x + rowsrc[r1] + kof + f40);
            cpa16(sptr(Bbuf + bi * 4608 + r1 * 36 + f40), g_qwr + (size_t)(n0 + r1) * 128 + kof + f40);
            asm volatile("cp.async.commit_group;");
            asm volatile("cp.async.wait_group 1;");
        } else {
            asm volatile("cp.async.wait_group 0;");
        }
        __syncthreads();
        gemm1_core(Abuf + (kc & 1) * 4608, Bbuf + (kc & 1) * 4608, lane, wm, wn, d);
        __syncthreads();
    }

    #pragma unroll
    for (int mi = 0; mi < 2; mi++) {
        int row = m0 + wm * 32 + mi * 16 + (lane >> 2);
        #pragma unroll
        for (int nj = 0; nj < 4; nj++) {
            int col = n0 + wn * 32 + nj * 8 + (lane & 3) * 2;
            float sc = (col < 128) ? 0.25503486f : 1.0f;   // hd^-0.5 * log2e
            float2 bv = *(const float2*)(bias + col);
            __half2 h0 = __floats2half2_rn((d[mi][nj][0] + bv.x) * sc,
                                           (d[mi][nj][1] + bv.y) * sc);
            __half2 h1 = __floats2half2_rn((d[mi][nj][2] + bv.x) * sc,
                                           (d[mi][nj][3] + bv.y) * sc);
            *(__half2*)(g_qkvh + (size_t)row * 384 + col) = h0;
            *(__half2*)(g_qkvh + (size_t)(row + 8) * 384 + col) = h1;
        }
    }
}

// ---------------------------------------------------------------------------
// Attention per-warp core (fp16 m16n8k16), templated on mask presence.
// ---------------------------------------------------------------------------
template<bool MASKED>
__device__ __forceinline__ void attn_tile(
    int mt, int lane, int win, int head,
    const __half* qbaseh, const unsigned char* rid,
    unsigned ksb, unsigned vtb)
{
    int qr = mt * 16 + (lane >> 2);
    int qc0 = (qr < 392) ? qr : 391;
    int qc1 = (qr + 8 < 392) ? (qr + 8) : 391;

    // Q A-fragments (2 x k16): raw fp16 pairs straight from gmem
    unsigned aq[2][4];
    {
        const unsigned* q0p = (const unsigned*)(qbaseh + (size_t)qc0 * 384) + (lane & 3);
        const unsigned* q1p = (const unsigned*)(qbaseh + (size_t)qc1 * 384) + (lane & 3);
        #pragma unroll
        for (int kk = 0; kk < 2; kk++) {
            aq[kk][0] = __ldg(q0p + kk * 8);
            aq[kk][1] = __ldg(q1p + kk * 8);
            aq[kk][2] = __ldg(q0p + kk * 8 + 4);
            aq[kk][3] = __ldg(q1p + kk * 8 + 4);
        }
    }

    unsigned char rq0 = 0, rq1 = 0;
    if (MASKED) { rq0 = rid[qc0]; rq1 = rid[qc1]; }
    const float4* bb = g_rpbT + ((head * 25 + mt) * 50) * 32 + lane;

    float oacc[4][4];
    #pragma unroll
    for (int dt = 0; dt < 4; dt++)
        #pragma unroll
        for (int r = 0; r < 4; r++) oacc[dt][r] = 0.f;
    float rs0 = 0.f, rs1 = 0.f;

    float4 bvA = __ldg(bb);
    float4 bvB = __ldg(bb + 32);

    #pragma unroll 2
    for (int p = 0; p < 25; p++) {
        float4 nA, nB;
        if (p < 24) {
            nA = __ldg(bb + (2 * p + 2) * 32);
            nB = __ldg(bb + (2 * p + 3) * 32);
        }
        // S accumulators init with (masked) bias
        float sA[4], sB[4];
        if (MASKED) {
            int jc = p * 16 + 2 * (lane & 3);
            unsigned char ra0 = rid[jc], ra1 = rid[jc + 1];
            unsigned char rb0 = rid[jc + 8], rb1 = rid[jc + 9];
            sA[0] = (rq0 == ra0) ? bvA.x : -1e4f;
            sA[1] = (rq0 == ra1) ? bvA.y : -1e4f;
            sA[2] = (rq1 == ra0) ? bvA.z : -1e4f;
            sA[3] = (rq1 == ra1) ? bvA.w : -1e4f;
            sB[0] = (rq0 == rb0) ? bvB.x : -1e4f;
            sB[1] = (rq0 == rb1) ? bvB.y : -1e4f;
            sB[2] = (rq1 == rb0) ? bvB.z : -1e4f;
            sB[3] = (rq1 == rb1) ? bvB.w : -1e4f;
        } else {
            sA[0] = bvA.x; sA[1] = bvA.y; sA[2] = bvA.z; sA[3] = bvA.w;
            sB[0] = bvB.x; sB[1] = bvB.y; sB[2] = bvB.z; sB[3] = bvB.w;
        }
        // S = Q K^T for the two 8-j tiles of this 16-j window
        unsigned kbA = ksb + (unsigned)p * 1280;     // 16 rows * 80 B
        unsigned b0[4], b1[4];
        ldsm4(b0, kbA);
        ldsm4(b1, kbA + 640);                        // +8 rows
        mmah(sA, aq[0], b0); mmah(sA, aq[1], b0 + 2);
        mmah(sB, aq[0], b1); mmah(sB, aq[1], b1 + 2);
        // exp2
        float e0A = ex2(sA[0]), e1A = ex2(sA[1]), e2A = ex2(sA[2]), e3A = ex2(sA[3]);
        float e0B = ex2(sB[0]), e1B = ex2(sB[1]), e2B = ex2(sB[2]), e3B = ex2(sB[3]);
        rs0 += (e0A + e1A) + (e0B + e1B);
        rs1 += (e2A + e3A) + (e2B + e3B);
        // C-frag -> fp16 A-frag: pure local pack
        unsigned pa[4];
        pa[0] = h2u(e0A, e1A);
        pa[1] = h2u(e2A, e3A);
        pa[2] = h2u(e0B, e1B);
        pa[3] = h2u(e2B, e3B);
        // PV: P(16x16) x V(16x32)
        unsigned vb = vtb + (unsigned)p * 32;
        unsigned v0[4], v1[4];
        ldsm4(v0, vb);
        ldsm4(v1, vb + 16 * 816);                    // d 16..31
        mmah(oacc[0], pa, v0); mmah(oacc[1], pa, v0 + 2);
        mmah(oacc[2], pa, v1); mmah(oacc[3], pa, v1 + 2);
        bvA = nA; bvB = nB;
    }

    rs0 += __shfl_xor_sync(0xffffffffu, rs0, 1);
    rs0 += __shfl_xor_sync(0xffffffffu, rs0, 2);
    rs1 += __shfl_xor_sync(0xffffffffu, rs1, 1);
    rs1 += __shfl_xor_sync(0xffffffffu, rs1, 2);
    float si0 = 1.f / rs0, si1 = 1.f / rs1;

    size_t ob = ((size_t)win * 392 + qr) * 128 + head * 32;
    #pragma unroll
    for (int dt = 0; dt < 4; dt++) {
        int dc = dt * 8 + 2 * (lane & 3);
        *(__half2*)(g_atth + ob + dc) =
            __floats2half2_rn(oacc[dt][0] * si0, oacc[dt][1] * si0);
        if (qr + 8 < 392) {
            *(__half2*)(g_atth + ob + 8 * 128 + dc) =
                __floats2half2_rn(oacc[dt][2] * si1, oacc[dt][3] * si1);
        }
    }
}

// ---------------------------------------------------------------------------
// Kernel 2: single-pass flash attention (fp16). 416 thr (13 warps), 1 sync.
// Smem: Ksh[400][40]h | Vth[32][408]h | rid[400]  = 58,512 B -> 2 blocks/SM
// ---------------------------------------------------------------------------
__global__ __launch_bounds__(416, 2) void attn_kernel()
{
    extern __shared__ __align__(16) char smc[];
    __half* Ksh = (__half*)smc;                      // 32,000 B
    __half* Vth = (__half*)(smc + 32000);            // 26,112 B
    unsigned char* rid = (unsigned char*)(smc + 32000 + 26112);  // 400

    int bx = blockIdx.x;
    int win = bx >> 2, head = bx & 3;
    int tid = threadIdx.x;

    const __half* qbaseh = g_qkvh + (size_t)win * (392 * 384) + head * 32;
    const __half* kbaseh = qbaseh + 128;
    const __half* vbaseh = qbaseh + 256;

    int w2 = win & 127;
    int bt = ((w2 >> 6) == 1), bh = (((w2 >> 3) & 7) == 7), bw = ((w2 & 7) == 7);
    bool masked = bt || bh || bw;
    for (int l = tid; l < 400; l += 416) {
        unsigned char v = 255;
        if (l < 392) {
            int lt = l / 49; int r = l - lt * 49; int lh = r / 7; int lw = r - lh * 7;
            int rt = bt ? ((lt < 4) ? 1 : 2) : 0;
            int rh = bh ? ((lh < 4) ? 1 : 2) : 0;
            int rw = bw ? ((lw < 4) ? 1 : 2) : 0;
            v = (unsigned char)(rt * 9 + rh * 3 + rw);
        }
        rid[l] = v;
    }
    // K rows: straight fp16 copy, 16B vectors (pad rows 392..399 = 0)
    for (int i = tid; i < 400 * 4; i += 416) {
        int j = i >> 2, c = i & 3;                   // c: 8-half chunk
        uint4 v = (j < 392) ? *(const uint4*)(kbaseh + (size_t)j * 384 + c * 8)
                            : make_uint4(0, 0, 0, 0);
        *(uint4*)(Ksh + j * 40 + c * 8) = v;
    }
    // V transposed fp16 (pad j 392..407 = 0); half2 loads, 2 scalar stores
    for (int i = tid; i < 16 * 408; i += 416) {
        int d2 = i / 408, j = i - d2 * 408;
        __half2 hv = (j < 392) ? *(const __half2*)(vbaseh + (size_t)j * 384 + d2 * 2)
                               : __floats2half2_rn(0.f, 0.f);
        Vth[(2 * d2) * 408 + j]     = __low2half(hv);
        Vth[(2 * d2 + 1) * 408 + j] = __high2half(hv);
    }
    __syncthreads();   // the only block-wide sync

    int lane = tid & 31, warp = tid >> 5;
    unsigned ksb = sptr(Ksh) + (lane & 7) * 80 + (lane >> 3) * 16;
    unsigned vtb = sptr(Vth) + (((lane >> 4) & 1) * 8 + (lane & 7)) * 816
                             + ((lane >> 3) & 1) * 16;

    if (masked) {
        for (int mt = warp; mt < 25; mt += 13)
            attn_tile<true>(mt, lane, win, head, qbaseh, rid, ksb, vtb);
    } else {
        for (int mt = warp; mt < 25; mt += 13)
            attn_tile<false>(mt, lane, win, head, qbaseh, rid, ksb, vtb);
    }
}

// ---------------------------------------------------------------------------
// Kernel 3: proj GEMM (fp16 m16n8k16), cp.async double-buffered, fused scatter.
// Smem: Ah[2][128*40]h | Bh[2][128*40]h | rowdst  = 41,472 B
// ---------------------------------------------------------------------------
__global__ __launch_bounds__(512, 2) void proj_kernel(
    const float* __restrict__ bias, float* __restrict__ out)
{
    extern __shared__ __align__(16) char smc[];
    __half* Ah = (__half*)smc;                       // [2][5120]
    __half* Bh = (__half*)(smc + 20480);             // [2][5120]
    int* rowdst = (int*)(smc + 40960);

    int m0 = blockIdx.x * 128;
    int tid = threadIdx.x;
    if (tid < 128) rowdst[tid] = token_img_offset(m0 + tid);
    __syncthreads();

    int lane = tid & 31, warp = tid >> 5;
    int wm = warp >> 2, wn = warp & 3;

    float d[2][4][4];
    #pragma unroll
    for (int mi = 0; mi < 2; mi++)
        #pragma unroll
        for (int nj = 0; nj < 4; nj++)
            #pragma unroll
            for (int r = 0; r < 4; r++) d[mi][nj][r] = 0.f;

    int rr = tid >> 2, pc = tid & 3;    // row 0..127, 8-half piece 0..3

    {   // kc=0 into buf 0
        cpa16(sptr(Ah + rr * 40 + pc * 8), g_atth + (size_t)(m0 + rr) * 128 + pc * 8);
        cpa16(sptr(Bh + rr * 40 + pc * 8), g_pwrh + (size_t)rr * 128 + pc * 8);
        asm volatile("cp.async.commit_group;");
    }
    #pragma unroll
    for (int kc = 0; kc < 4; kc++) {
        if (kc < 3) {
            int bi = (kc + 1) & 1, kof = (kc + 1) * 32;
            cpa16(sptr(Ah + bi * 5120 + rr * 40 + pc * 8),
                  g_atth + (size_t)(m0 + rr) * 128 + kof + pc * 8);
            cpa16(sptr(Bh + bi * 5120 + rr * 40 + pc * 8),
                  g_pwrh + (size_t)rr * 128 + kof + pc * 8);
            asm volatile("cp.async.commit_group;");
            asm volatile("cp.async.wait_group 1;");
        } else {
            asm volatile("cp.async.wait_group 0;");
        }
        __syncthreads();

        __half* Ab = Ah + (kc & 1) * 5120;
        __half* Bb = Bh + (kc & 1) * 5120;
        unsigned aoff = sptr(Ab) + (wm * 32 + (lane & 15)) * 80 + ((lane >> 4) & 1) * 16;
        unsigned boff = sptr(Bb) + (wn * 32 + (lane & 7)) * 80 + (lane >> 3) * 16;

        unsigned a[2][2][4];     // [mi][kk]
        #pragma unroll
        for (int mi = 0; mi < 2; mi++)
            #pragma unroll
            for (int kk = 0; kk < 2; kk++)
                ldsm4(a[mi][kk], aoff + mi * (16 * 80) + kk * 32);
        unsigned b[4][4];        // [nj]: 2 frags (kk) each
        #pragma unroll
        for (int nj = 0; nj < 4; nj++)
            ldsm4(b[nj], boff + nj * (8 * 80));

        #pragma unroll
        for (int kk = 0; kk < 2; kk++)
            #pragma unroll
            for (int mi = 0; mi < 2; mi++)
                #pragma unroll
                for (int nj = 0; nj < 4; nj++)
                    mmah(d[mi][nj], a[mi][kk], b[nj] + 2 * kk);
        __syncthreads();
    }

    #pragma unroll
    for (int mi = 0; mi < 2; mi++) {
        int ml = wm * 32 + mi * 16 + (lane >> 2);
        #pragma unroll
        for (int nj = 0; nj < 4; nj++) {
            int col = wn * 32 + nj * 8 + (lane & 3) * 2;
            float2 bvv = *(const float2*)(bias + col);
            float2 o0, o1;
            o0.x = d[mi][nj][0] + bvv.x; o0.y = d[mi][nj][1] + bvv.y;
            o1.x = d[mi][nj][2] + bvv.x; o1.y = d[mi][nj][3] + bvv.y;
            *(float2*)(out + rowdst[ml] + col) = o0;
            *(float2*)(out + rowdst[ml + 8] + col) = o1;
        }
    }
}

// ---------------------------------------------------------------------------
extern "C" void kernel_launch(void* const* d_in, const int* in_sizes, int n_in,
                              void* d_out, int out_size)
{
    const float* x   = (const float*)d_in[0];
    const float* qw  = (const float*)d_in[1];
    const float* qb  = (const float*)d_in[2];
    const float* pw  = (const float*)d_in[3];
    const float* pb  = (const float*)d_in[4];
    const float* rpb = (const float*)d_in[5];
    float* out = (float*)d_out;

    const int smemG = 4 * 4608 * 4 + 512;    // 74,240 B
    const int smemA = 32000 + 26112 + 400;   // 58,512 B
    const int smemP = 40960 + 512;           // 41,472 B

    cudaFuncSetAttribute(qkv_kernel,  cudaFuncAttributeMaxDynamicSharedMemorySize, smemG);
    cudaFuncSetAttribute(attn_kernel, cudaFuncAttributeMaxDynamicSharedMemorySize, smemA);
    cudaFuncSetAttribute(proj_kernel, cudaFuncAttributeMaxDynamicSharedMemorySize, smemP);

    prep_kernel<<<881, 256>>>(rpb, qw, pw);
    qkv_kernel<<<dim3(3, 784), 512, smemG>>>(x, qb);
    attn_kernel<<<1024, 416, smemA>>>();
    proj_kernel<<<784, 512, smemP>>>(pb, out);
}